// round 10
// baseline (speedup 1.0000x reference)
#include <cuda_runtime.h>
#include <cuda_fp16.h>
#include <cstdint>

typedef unsigned int u32;

// ---------------------------------------------------------------------------
// Problem constants
// ---------------------------------------------------------------------------
#define DMODEL 1024
#define NHEAD  16
#define HDIM   64
#define CA     384
#define TT     16
#define BB     4
#define LL     257
#define BT     (BB*TT)            // 64
#define MROWS  (BT*LL)            // 16448
#define MOFF   (BT*(LL-1))        // 16384

// ---------------------------------------------------------------------------
// Scratch (static __device__ arrays; no dynamic allocation allowed)
// ---------------------------------------------------------------------------
__device__ float  g_x1  [(size_t)MROWS*DMODEL];
__device__ float  g_x2  [(size_t)MROWS*DMODEL];
__device__ __half h_off2[(size_t)MOFF*DMODEL];
__device__ __half h_y2  [(size_t)MROWS*DMODEL];
__device__ __half h_qkv [(size_t)MROWS*3*DMODEL];
__device__ __half h_ln  [(size_t)MROWS*DMODEL];
__device__ __half h_attn[(size_t)MROWS*DMODEL];
__device__ __half h_x1  [(size_t)MROWS*DMODEL];
__device__ __half h_diff[(size_t)MOFF*DMODEL];
__device__ __half h_off1[(size_t)MOFF*CA];
__device__ __half h_offc[(size_t)MOFF*CA];
__device__ __half h_y1  [(size_t)MROWS*CA];
__device__ __half h_yc  [(size_t)MROWS*CA];
__device__ __half h_h   [(size_t)MROWS*4*DMODEL];
__device__ __half wh_in  [3*DMODEL*DMODEL];
__device__ __half wh_out [DMODEL*DMODEL];
__device__ __half wh_ofc1[CA*DMODEL];
__device__ __half wh_ofc2[DMODEL*CA];
__device__ __half wh_afc1[CA*DMODEL];
__device__ __half wh_afc2[DMODEL*CA];
__device__ __half wh_mfc [4*DMODEL*DMODEL];
__device__ __half wh_mpj [DMODEL*4*DMODEL];

// ---------------------------------------------------------------------------
// helpers
// ---------------------------------------------------------------------------
__device__ __forceinline__ u32 smem_u32(const void* p) {
    u32 a;
    asm("{ .reg .u64 t; cvta.to.shared.u64 t, %1; cvt.u32.u64 %0, t; }"
        : "=r"(a) : "l"(p));
    return a;
}

__device__ __forceinline__ void ldmx4(u32& r0, u32& r1, u32& r2, u32& r3, u32 addr) {
    asm volatile("ldmatrix.sync.aligned.m8n8.x4.shared.b16 {%0,%1,%2,%3}, [%4];"
                 : "=r"(r0), "=r"(r1), "=r"(r2), "=r"(r3) : "r"(addr));
}

__device__ __forceinline__ void mma16816(float* c, u32 a0, u32 a1, u32 a2, u32 a3,
                                         u32 b0, u32 b1) {
    asm volatile(
        "mma.sync.aligned.m16n8k16.row.col.f32.f16.f16.f32 "
        "{%0,%1,%2,%3}, {%4,%5,%6,%7}, {%8,%9}, {%0,%1,%2,%3};\n"
        : "+f"(c[0]), "+f"(c[1]), "+f"(c[2]), "+f"(c[3])
        : "r"(a0), "r"(a1), "r"(a2), "r"(a3), "r"(b0), "r"(b1));
}

__device__ __forceinline__ u32 h2u(__half2 v) {
    return *reinterpret_cast<u32*>(&v);
}

// exp2 via degree-6 poly (rel err ~1e-5), FMA pipe only (no MUFU)
__device__ __forceinline__ float exp2p(float y) {
    y = fminf(fmaxf(y, -120.f), 88.f);
    int n = __float2int_rd(y);
    float f = y - (float)n;
    float p = 1.54035304e-4f;
    p = fmaf(p, f, 1.33335581e-3f);
    p = fmaf(p, f, 9.61812910e-3f);
    p = fmaf(p, f, 5.55041087e-2f);
    p = fmaf(p, f, 2.40226507e-1f);
    p = fmaf(p, f, 6.93147181e-1f);
    p = fmaf(p, f, 1.0f);
    return __int_as_float((n + 127) << 23) * p;
}

// ---------------------------------------------------------------------------
// fp32 -> fp16 weight conversion: ALL 8 weight tensors in ONE launch
// ---------------------------------------------------------------------------
struct F2HArgs {
    const float* src[8];
    __half*      dst[8];
    int          n4[8];
};

__global__ void f2h_oct(F2HArgs args)
{
    int i = blockIdx.x * blockDim.x + threadIdx.x;
    int j = i;
#pragma unroll
    for (int t = 0; t < 8; t++) {
        if (j < args.n4[t]) {
            float4 v = *(const float4*)(args.src[t] + (size_t)j * 4);
            __half2* o = (__half2*)(args.dst[t] + (size_t)j * 4);
            o[0] = __floats2half2_rn(v.x, v.y);
            o[1] = __floats2half2_rn(v.z, v.w);
            return;
        }
        j -= args.n4[t];
    }
}

// ---------------------------------------------------------------------------
// LayerNorm: one block per row, fp16 output
// ---------------------------------------------------------------------------
__global__ __launch_bounds__(256) void ln_kernel(
    const float* __restrict__ x, const float* __restrict__ gw,
    const float* __restrict__ bw, __half* __restrict__ y)
{
    __shared__ float red0[8], red1[8];
    const int row = blockIdx.x;
    const int tid = threadIdx.x;
    const float* xr = x + (size_t)row * DMODEL;
    float v[4];
    float s = 0.f, s2 = 0.f;
#pragma unroll
    for (int i = 0; i < 4; i++) {
        v[i] = xr[tid + i * 256];
        s += v[i];
        s2 += v[i] * v[i];
    }
#pragma unroll
    for (int o = 16; o > 0; o >>= 1) {
        s  += __shfl_xor_sync(0xffffffffu, s,  o);
        s2 += __shfl_xor_sync(0xffffffffu, s2, o);
    }
    if ((tid & 31) == 0) { red0[tid >> 5] = s; red1[tid >> 5] = s2; }
    __syncthreads();
    if (tid < 32) {
        float a  = (tid < 8) ? red0[tid] : 0.f;
        float a2 = (tid < 8) ? red1[tid] : 0.f;
#pragma unroll
        for (int o = 4; o > 0; o >>= 1) {
            a  += __shfl_xor_sync(0xffffffffu, a,  o);
            a2 += __shfl_xor_sync(0xffffffffu, a2, o);
        }
        if (tid == 0) { red0[0] = a; red1[0] = a2; }
    }
    __syncthreads();
    const float mean = red0[0] * (1.f / DMODEL);
    const float var  = red1[0] * (1.f / DMODEL) - mean * mean;
    const float inv  = rsqrtf(var + 1e-5f);
    __half* yr = y + (size_t)row * DMODEL;
#pragma unroll
    for (int i = 0; i < 4; i++) {
        int d = tid + i * 256;
        yr[d] = __float2half_rn((v[i] - mean) * inv * gw[d] + bw[d]);
    }
}

// ---------------------------------------------------------------------------
// Fused combine + LayerNorm2: x2 = x1 + y2 + scatter(off2); lnh = LN(x2)
// y2 / off2 now fp16 (adapter outputs are small; precision unaffected)
// ---------------------------------------------------------------------------
__global__ __launch_bounds__(256) void combine_ln_kernel(
    const float* __restrict__ x1, const __half* __restrict__ y2,
    const __half* __restrict__ off2,
    const float* __restrict__ gw, const float* __restrict__ bw,
    float* __restrict__ x2, __half* __restrict__ yln)
{
    __shared__ float red0[8], red1[8];
    const int row = blockIdx.x;
    const int l  = row % LL;
    const int bt = row / LL;
    const int tid = threadIdx.x;
    const size_t rb = (size_t)row * DMODEL;
    const __half* offr = (l > 0) ? off2 + ((size_t)(bt * 256 + l - 1)) * DMODEL : nullptr;

    float v[4];
    float s = 0.f, s2 = 0.f;
#pragma unroll
    for (int i = 0; i < 4; i++) {
        int d = tid + i * 256;
        float a = x1[rb + d] + __half2float(y2[rb + d]);
        if (offr) a += __half2float(offr[d]);
        v[i] = a;
        x2[rb + d] = a;
        s += a;
        s2 += a * a;
    }
#pragma unroll
    for (int o = 16; o > 0; o >>= 1) {
        s  += __shfl_xor_sync(0xffffffffu, s,  o);
        s2 += __shfl_xor_sync(0xffffffffu, s2, o);
    }
    if ((tid & 31) == 0) { red0[tid >> 5] = s; red1[tid >> 5] = s2; }
    __syncthreads();
    if (tid < 32) {
        float a  = (tid < 8) ? red0[tid] : 0.f;
        float a2 = (tid < 8) ? red1[tid] : 0.f;
#pragma unroll
        for (int o = 4; o > 0; o >>= 1) {
            a  += __shfl_xor_sync(0xffffffffu, a,  o);
            a2 += __shfl_xor_sync(0xffffffffu, a2, o);
        }
        if (tid == 0) { red0[0] = a; red1[0] = a2; }
    }
    __syncthreads();
    const float mean = red0[0] * (1.f / DMODEL);
    const float var  = red1[0] * (1.f / DMODEL) - mean * mean;
    const float inv  = rsqrtf(var + 1e-5f);
    __half* yr = yln + rb;
#pragma unroll
    for (int i = 0; i < 4; i++) {
        int d = tid + i * 256;
        yr[d] = __float2half_rn((v[i] - mean) * inv * gw[d] + bw[d]);
    }
}

// ---------------------------------------------------------------------------
// Pipelined fp16 GEMM body (proven)
// EPI: 0 bias->f32 | 1 bias+res->f32+f16 | 2 bias+gelu->f16 | 3 bias+res->f32
//      4 bias->f16 only
// ---------------------------------------------------------------------------
#define GBM 128
#define GBN 128
#define GBK 64
#define STG_HALVES (128*64)
#define GEMM_SMEM  (3 * 2 * STG_HALVES * 2)
#define GELU_C (-2.4553766f)   /* -1.702 * log2(e) */

__device__ __forceinline__ void gemm_stage_load(
    const __half* __restrict__ A, const __half* __restrict__ W,
    int M, int K, int m0, int n0, int kt, u32 sA, u32 sB, int tid)
{
#pragma unroll
    for (int i = 0; i < 4; i++) {
        int cid = tid + i * 256;
        int row = cid >> 3, c = cid & 7;
        int sw  = ((c ^ (row & 7)) << 3);
        const __half* srcA = A + (size_t)(m0 + row) * K + kt * GBK + c * 8;
        u32 dA = sA + (u32)(row * 64 + sw) * 2;
        int szA = (m0 + row < M) ? 16 : 0;
        asm volatile("cp.async.cg.shared.global [%0], [%1], 16, %2;\n"
                     :: "r"(dA), "l"(srcA), "r"(szA));
        const __half* srcB = W + (size_t)(n0 + row) * K + kt * GBK + c * 8;
        u32 dB = sB + (u32)(row * 64 + sw) * 2;
        asm volatile("cp.async.cg.shared.global [%0], [%1], 16, 16;\n"
                     :: "r"(dB), "l"(srcB));
    }
    asm volatile("cp.async.commit_group;\n");
}

template <int EPI>
__device__ __forceinline__ void gemm_body(
    const __half* __restrict__ A, const __half* __restrict__ W,
    const float* __restrict__ bias, const float* __restrict__ res,
    float* __restrict__ C, __half* __restrict__ Ch,
    int M, int N, int K)
{
    extern __shared__ __half smh[];
    const u32 sbase = smem_u32(smh);

    const int tid    = threadIdx.x;
    const int lane   = tid & 31;
    const int wid    = tid >> 5;
    const int warp_m = wid & 3;
    const int warp_n = wid >> 2;
    const int m0 = blockIdx.y * GBM;
    const int n0 = blockIdx.x * GBN;
    const int mIdx = lane >> 3;
    const int rIn  = lane & 7;

    float acc[2][8][4];
#pragma unroll
    for (int i = 0; i < 2; i++)
#pragma unroll
        for (int j = 0; j < 8; j++)
#pragma unroll
            for (int k = 0; k < 4; k++) acc[i][j][k] = 0.f;

    const int ktiles = K / GBK;

    gemm_stage_load(A, W, M, K, m0, n0, 0, sbase, sbase + 3u*STG_HALVES*2, tid);
    gemm_stage_load(A, W, M, K, m0, n0, 1, sbase + 1u*STG_HALVES*2, sbase + 4u*STG_HALVES*2, tid);

    for (int kt = 0; kt < ktiles; kt++) {
        asm volatile("cp.async.wait_group 1;\n" ::: "memory");
        __syncthreads();

        if (kt + 2 < ktiles) {
            int slot = (kt + 2) % 3;
            gemm_stage_load(A, W, M, K, m0, n0, kt + 2,
                            sbase + (u32)slot * STG_HALVES * 2,
                            sbase + (u32)(3 + slot) * STG_HALVES * 2, tid);
        } else {
            asm volatile("cp.async.commit_group;\n");
        }

        const int slot = kt % 3;
        const u32 sA = sbase + (u32)slot * STG_HALVES * 2;
        const u32 sB = sbase + (u32)(3 + slot) * STG_HALVES * 2;

#pragma unroll
        for (int ks = 0; ks < 4; ks++) {
            u32 a00, a01, a02, a03, a10, a11, a12, a13;
            {
                int row   = warp_m * 32 + (mIdx & 1) * 8 + rIn;
                int chunk = ks * 2 + (mIdx >> 1);
                u32 ad0 = sA + (u32)(row * 64 + ((chunk ^ (row & 7)) << 3)) * 2;
                ldmx4(a00, a01, a02, a03, ad0);
                int row1 = row + 16;
                u32 ad1 = sA + (u32)(row1 * 64 + ((chunk ^ (row1 & 7)) << 3)) * 2;
                ldmx4(a10, a11, a12, a13, ad1);
            }
#pragma unroll
            for (int j = 0; j < 4; j++) {
                int nrow  = warp_n * 64 + j * 16 + (mIdx >> 1) * 8 + rIn;
                int chunk = ks * 2 + (mIdx & 1);
                u32 badr = sB + (u32)(nrow * 64 + ((chunk ^ (nrow & 7)) << 3)) * 2;
                u32 b0, b1, b2, b3;
                ldmx4(b0, b1, b2, b3, badr);
                mma16816(acc[0][2*j],   a00, a01, a02, a03, b0, b1);
                mma16816(acc[0][2*j+1], a00, a01, a02, a03, b2, b3);
                mma16816(acc[1][2*j],   a10, a11, a12, a13, b0, b1);
                mma16816(acc[1][2*j+1], a10, a11, a12, a13, b2, b3);
            }
        }
        // no trailing sync needed with 3-deep ring
    }

    const int g  = lane >> 2;
    const int tg = lane & 3;
#pragma unroll
    for (int mi = 0; mi < 2; mi++) {
#pragma unroll
        for (int ni = 0; ni < 8; ni++) {
            const int col = n0 + warp_n * 64 + ni * 8 + tg * 2;
            const float bc0 = bias[col], bc1 = bias[col + 1];
#pragma unroll
            for (int hh = 0; hh < 2; hh++) {
                int row = m0 + warp_m * 32 + mi * 16 + g + hh * 8;
                if (row < M) {
                    float v0 = acc[mi][ni][hh * 2 + 0] + bc0;
                    float v1 = acc[mi][ni][hh * 2 + 1] + bc1;
                    if (EPI == 2) {
                        v0 = __fdividef(v0, 1.f + exp2p(GELU_C * v0));
                        v1 = __fdividef(v1, 1.f + exp2p(GELU_C * v1));
                        *(__half2*)(Ch + (size_t)row * N + col) = __floats2half2_rn(v0, v1);
                    } else if (EPI == 4) {
                        *(__half2*)(Ch + (size_t)row * N + col) = __floats2half2_rn(v0, v1);
                    } else {
                        if (EPI == 1 || EPI == 3) {
                            const float2 rr = *(const float2*)(res + (size_t)row * N + col);
                            v0 += rr.x; v1 += rr.y;
                        }
                        *(float2*)(C + (size_t)row * N + col) = make_float2(v0, v1);
                        if (EPI == 1)
                            *(__half2*)(Ch + (size_t)row * N + col) = __floats2half2_rn(v0, v1);
                    }
                }
            }
        }
    }
}

template <int EPI>
__global__ __launch_bounds__(256, 2) void gemm16(
    const __half* __restrict__ A, const __half* __restrict__ W,
    const float* __restrict__ bias, const float* __restrict__ res,
    float* __restrict__ C, __half* __restrict__ Ch,
    int M, int N, int K)
{
    gemm_body<EPI>(A, W, bias, res, C, Ch, M, N, K);
}

// dual-problem GEMM (fills partial waves of small grids)
template <int EPI>
__global__ __launch_bounds__(256, 2) void gemm16_dual(
    const __half* __restrict__ A0, const __half* __restrict__ W0,
    const float* __restrict__ b0, float* __restrict__ C0, __half* __restrict__ Ch0, int M0,
    const __half* __restrict__ A1, const __half* __restrict__ W1,
    const float* __restrict__ b1, float* __restrict__ C1, __half* __restrict__ Ch1, int M1,
    int N, int K)
{
    if (blockIdx.z == 0)
        gemm_body<EPI>(A0, W0, b0, nullptr, C0, Ch0, M0, N, K);
    else
        gemm_body<EPI>(A1, W1, b1, nullptr, C1, Ch1, M1, N, K);
}

// ---------------------------------------------------------------------------
// Tensor-core flash attention v3: TWO CTAs per (bt, head), 288 threads each
// (9 warps). Half 0 covers query tiles 0-8, half 1 tiles 9-16. Each CTA
// stages only its 144 Q rows + full K + V^T -> 95.7 KB smem, ~27K regs
// => 2 CTAs/SM, so staging overlaps compute across co-resident CTAs.
// ---------------------------------------------------------------------------
#define AT_THREADS 288
#define QK_ROW 72
#define VT_ROW 280
#define NKT    17
#define QROWS  144                 /* 9 tiles of 16 */
#define SK_OFF  (QROWS*QK_ROW)                  // 10368
#define SVT_OFF (SK_OFF + 272*QK_ROW)           // 29952
#define ATTN_SMEM ((SVT_OFF + HDIM*VT_ROW) * 2) // 95744 B
#define QSC 0.1803368801111244f   /* hd^-0.5 * log2(e) */

__global__ __launch_bounds__(AT_THREADS, 2) void attn_mma(
    const __half* __restrict__ qkvh, __half* __restrict__ out)
{
    extern __shared__ __half smA[];
    __half* sQh  = smA;
    __half* sKh  = smA + SK_OFF;
    __half* sVth = smA + SVT_OFF;
    const u32 sQ  = smem_u32(smA);
    const u32 sK  = sQ + SK_OFF * 2;
    const u32 sVt = sQ + SVT_OFF * 2;

    const int bid  = blockIdx.x;
    const int bt   = bid >> 5;
    const int h    = (bid >> 1) & 15;
    const int half = bid & 1;
    const int qbase = half * QROWS;
    const int tid = threadIdx.x;
    const __half* base = qkvh + (size_t)bt * LL * (3 * DMODEL) + h * HDIM;

    // stage K (rows 0..256) and V^T (cols 0..256)
    for (int i = tid; i < LL * 16; i += AT_THREADS) {
        int l = i >> 4, d4 = i & 15;
        const __half* p = base + (size_t)l * (3 * DMODEL) + d4 * 4;
        uint2 kr = *(const uint2*)(p + DMODEL);
        uint2 vr = *(const uint2*)(p + 2 * DMODEL);
        *(uint2*)(sKh + l * QK_ROW + d4 * 4) = kr;
        __half2 v01 = *(__half2*)&vr.x;
        __half2 v23 = *(__half2*)&vr.y;
        int d = d4 * 4;
        sVth[(d + 0) * VT_ROW + l] = __low2half(v01);
        sVth[(d + 1) * VT_ROW + l] = __high2half(v01);
        sVth[(d + 2) * VT_ROW + l] = __low2half(v23);
        sVth[(d + 3) * VT_ROW + l] = __high2half(v23);
    }
    // stage this CTA's Q rows (scaled), zero beyond LL
    for (int i = tid; i < QROWS * 16; i += AT_THREADS) {
        int lr = i >> 4, d4 = i & 15;
        int gl = qbase + lr;
        __half2 q0, q1;
        if (gl < LL) {
            const __half* p = base + (size_t)gl * (3 * DMODEL) + d4 * 4;
            uint2 qr = *(const uint2*)(p);
            float2 qa = __half22float2(*(__half2*)&qr.x);
            float2 qb = __half22float2(*(__half2*)&qr.y);
            q0 = __floats2half2_rn(qa.x * QSC, qa.y * QSC);
            q1 = __floats2half2_rn(qb.x * QSC, qb.y * QSC);
        } else {
            q0 = __floats2half2_rn(0.f, 0.f);
            q1 = q0;
        }
        __half2* qd = (__half2*)(sQh + lr * QK_ROW + d4 * 4);
        qd[0] = q0;
        qd[1] = q1;
    }
    // zero pads: K rows 257..271, V^T cols 257..271
    for (int i = tid; i < 15 * HDIM; i += AT_THREADS) {
        int l = LL + (i >> 6);
        int d = i & 63;
        __half z = __float2half(0.f);
        sKh[l * QK_ROW + d] = z;
        sVth[d * VT_ROW + l] = z;
    }
    __syncthreads();

    const int wid  = tid >> 5;          // 0..8
    const int lane = tid & 31;
    const int g    = lane >> 2;
    const int tg   = lane & 3;
    const int mIdx = lane >> 3;
    const int rIn  = lane & 7;
    const int qt   = half * 9 + wid;    // global query tile
    if (qt >= NKT) return;              // half 1, warp 8 idles (after staging)

    u32 aQ[4][4];
#pragma unroll
    for (int kc = 0; kc < 4; kc++) {
        int row   = wid * 16 + (mIdx & 1) * 8 + rIn;   // local row in sQ
        int chunk = kc * 2 + (mIdx >> 1);
        ldmx4(aQ[kc][0], aQ[kc][1], aQ[kc][2], aQ[kc][3],
              sQ + (u32)(row * QK_ROW + chunk * 8) * 2);
    }

    float m0 = -1e30f, m1 = -1e30f, l0 = 0.f, l1 = 0.f;
    float oacc[8][4];
#pragma unroll
    for (int n = 0; n < 8; n++)
#pragma unroll
        for (int j = 0; j < 4; j++) oacc[n][j] = 0.f;

    for (int kt = 0; kt < NKT; kt++) {
        float sf[2][4];
#pragma unroll
        for (int j = 0; j < 4; j++) { sf[0][j] = 0.f; sf[1][j] = 0.f; }
#pragma unroll
        for (int kc = 0; kc < 4; kc++) {
            int nrow  = kt * 16 + (mIdx >> 1) * 8 + rIn;
            int chunk = kc * 2 + (mIdx & 1);
            u32 b0, b1, b2, b3;
            ldmx4(b0, b1, b2, b3, sK + (u32)(nrow * QK_ROW + chunk * 8) * 2);
            mma16816(sf[0], aQ[kc][0], aQ[kc][1], aQ[kc][2], aQ[kc][3], b0, b1);
            mma16816(sf[1], aQ[kc][0], aQ[kc][1], aQ[kc][2], aQ[kc][3], b2, b3);
        }
        if (kt == 16) {   // only key 256 (local col 0, tg==0) is valid
            bool v0 = (tg == 0);
            sf[0][0] = v0 ? sf[0][0] : -1e30f;
            sf[0][2] = v0 ? sf[0][2] : -1e30f;
            sf[0][1] = -1e30f; sf[0][3] = -1e30f;
            sf[1][0] = -1e30f; sf[1][1] = -1e30f;
            sf[1][2] = -1e30f; sf[1][3] = -1e30f;
        }
        float tm0 = fmaxf(fmaxf(sf[0][0], sf[0][1]), fmaxf(sf[1][0], sf[1][1]));
        float tm1 = fmaxf(fmaxf(sf[0][2], sf[0][3]), fmaxf(sf[1][2], sf[1][3]));
        tm0 = fmaxf(tm0, __shfl_xor_sync(0xffffffffu, tm0, 1));
        tm0 = fmaxf(tm0, __shfl_xor_sync(0xffffffffu, tm0, 2));
        tm1 = fmaxf(tm1, __shfl_xor_sync(0xffffffffu, tm1, 1));
        tm1 = fmaxf(tm1, __shfl_xor_sync(0xffffffffu, tm1, 2));
        if (tm0 > m0) {
            float c = exp2p(m0 - tm0);
            m0 = tm0; l0 *= c;
#pragma unroll
            for (int n = 0; n < 8; n++) { oacc[n][0] *= c; oacc[n][1] *= c; }
        }
        if (tm1 > m1) {
            float c = exp2p(m1 - tm1);
            m1 = tm1; l1 *= c;
#pragma unroll
            for (int n = 0; n < 8; n++) { oacc[n][2] *= c; oacc[n][3] *= c; }
        }
        float p00 = exp2p(sf[0][0] - m0), p01 = exp2p(sf[0][1] - m0);
        float p02 = exp2p(sf[1][0] - m0), p03 = exp2p(sf[1][1] - m0);
        float p10 = exp2p(sf[0][2] - m1), p11 = exp2p(sf[0][3] - m1);
        float p12 = exp2p(sf[1][2] - m1), p13 = exp2p(sf[1][3] - m1);
        l0 += (p00 + p01) + (p02 + p03);
        l1 += (p10 + p11) + (p12 + p13);
        u32 aP0 = h2u(__floats2half2_rn(p00, p01));
        u32 aP1 = h2u(__floats2half2_rn(p10, p11));
        u32 aP2 = h2u(__floats2half2_rn(p02, p03));
        u32 aP3 = h2u(__floats2half2_rn(p12, p13));
#pragma unroll
        for (int np = 0; np < 4; np++) {
            int nrow  = np * 16 + (mIdx >> 1) * 8 + rIn;
            int chunk = kt * 2 + (mIdx & 1);
            u32 b0, b1, b2, b3;
            ldmx4(b0, b1, b2, b3, sVt + (u32)(nrow * VT_ROW + chunk * 8) * 2);
            mma16816(oacc[2*np],     aP0, aP1, aP2, aP3, b0, b1);
            mma16816(oacc[2*np + 1], aP0, aP1, aP2, aP3, b2, b3);
        }
    }
    l0 += __shfl_xor_sync(0xffffffffu, l0, 1);
    l0 += __shfl_xor_sync(0xffffffffu, l0, 2);
    l1 += __shfl_xor_sync(0xffffffffu, l1, 1);
    l1 += __shfl_xor_sync(0xffffffffu, l1, 2);
    float inv0 = 1.f / l0, inv1 = 1.f / l1;
    int r0 = qt * 16 + g;
    int r1 = r0 + 8;
    if (r0 < LL) {
        __half2* o = (__half2*)(out + ((size_t)bt * LL + r0) * DMODEL + h * HDIM);
#pragma unroll
        for (int n = 0; n < 8; n++)
            o[(n * 8 + tg * 2) >> 1] = __floats2half2_rn(oacc[n][0] * inv0, oacc[n][1] * inv0);
    }
    if (r1 < LL) {
        __half2* o = (__half2*)(out + ((size_t)bt * LL + r1) * DMODEL + h * HDIM);
#pragma unroll
        for (int n = 0; n < 8; n++)
            o[(n * 8 + tg * 2) >> 1] = __floats2half2_rn(oacc[n][2] * inv1, oacc[n][3] * inv1);
    }
}

// ---------------------------------------------------------------------------
// Elementwise / conv kernels
// ---------------------------------------------------------------------------
// temporal diff of patch tokens, fp16 in / fp16 out (half2 arithmetic)
__global__ void diff_kernel(const __half* __restrict__ x1h, __half* __restrict__ diff)
{
    int i = blockIdx.x * blockDim.x + threadIdx.x;   // 4 elems per thread
    if (i >= MOFF * DMODEL / 4) return;
    int r = i >> 8;
    int p = r & 255;
    int f = r >> 8;
    int t = f & (TT - 1);
    size_t cur = ((size_t)f * LL + (p + 1)) * DMODEL + (size_t)(i & 255) * 4;
    uint2 v = *(const uint2*)(x1h + cur);
    uint2 pv = (t > 0) ? *(const uint2*)(x1h + cur - (size_t)LL * DMODEL) : v;
    __half2* o = (__half2*)(diff + (size_t)i * 4);
    o[0] = __hsub2(*(__half2*)&v.x, *(__half2*)&pv.x);
    o[1] = __hsub2(*(__half2*)&v.y, *(__half2*)&pv.y);
}

// merged depthwise convs (fp16 in/out)
__global__ void conv_merged(const __half* __restrict__ off1,
                            const float* __restrict__ ocw, const float* __restrict__ ocb,
                            __half* __restrict__ offc,
                            const __half* __restrict__ y1,
                            const float* __restrict__ acw, const float* __restrict__ acb,
                            __half* __restrict__ yc)
{
    int idx = blockIdx.x * blockDim.x + threadIdx.x;
    if (idx < MOFF * CA) {
        int c = idx % CA;
        int r = idx / CA;
        int p = r & 255;
        int n = r >> 8;
        int hh = p >> 4, ww = p & 15;
        float s = ocb[c];
#pragma unroll
        for (int dh = 0; dh < 3; dh++) {
            int h2 = hh + dh - 1;
            if (h2 < 0 || h2 > 15) continue;
#pragma unroll
            for (int dw = 0; dw < 3; dw++) {
                int w2 = ww + dw - 1;
                if (w2 < 0 || w2 > 15) continue;
                s += __half2float(off1[((size_t)(n * 256 + h2 * 16 + w2)) * CA + c])
                     * ocw[(dh * 3 + dw) * CA + c];
            }
        }
        offc[idx] = __float2half_rn(s);
    } else {
        int k = idx - MOFF * CA;
        if (k >= MROWS * CA) return;
        int c = k % CA;
        int row = k / CA;
        int l = row % LL;
        int bt = row / LL;
        int t = bt & (TT - 1);
        float s = acb[c];
#pragma unroll
        for (int dt = 0; dt < 3; dt++) {
            int tt = t + dt - 1;
            if (tt < 0 || tt >= TT) continue;
            s += __half2float(y1[((size_t)(bt + dt - 1) * LL + l) * CA + c]) * acw[dt * CA + c];
        }
        yc[k] = __float2half_rn(s);
    }
}

// ---------------------------------------------------------------------------
// Launch
// ---------------------------------------------------------------------------
extern "C" void kernel_launch(void* const* d_in, const int* in_sizes, int n_in,
                              void* d_out, int out_size)
{
    const float* x         = (const float*)d_in[0];
    const float* ln1_g     = (const float*)d_in[1];
    const float* ln1_b     = (const float*)d_in[2];
    const float* w_in      = (const float*)d_in[3];
    const float* b_in      = (const float*)d_in[4];
    const float* w_out     = (const float*)d_in[5];
    const float* b_out     = (const float*)d_in[6];
    const float* o_fc1_w   = (const float*)d_in[7];
    const float* o_fc1_b   = (const float*)d_in[8];
    const float* o_conv_w  = (const float*)d_in[9];
    const float* o_conv_b  = (const float*)d_in[10];
    const float* o_fc2_w   = (const float*)d_in[11];
    const float* o_fc2_b   = (const float*)d_in[12];
    const float* a_fc1_w   = (const float*)d_in[13];
    const float* a_fc1_b   = (const float*)d_in[14];
    const float* a_conv_w  = (const float*)d_in[15];
    const float* a_conv_b  = (const float*)d_in[16];
    const float* a_fc2_w   = (const float*)d_in[17];
    const float* a_fc2_b   = (const float*)d_in[18];
    const float* ln2_g     = (const float*)d_in[19];
    const float* ln2_b     = (const float*)d_in[20];
    const float* mlp_fc_w  = (const float*)d_in[21];
    const float* mlp_fc_b  = (const float*)d_in[22];
    const float* mlp_proj_w= (const float*)d_in[23];
    const float* mlp_proj_b= (const float*)d_in[24];
    float* outp = (float*)d_out;

    float *x1, *x2;
    __half *off2h, *y2h;
    __half *qkvh, *lnh, *attnh, *x1h, *diffh, *off1h, *offch, *y1h, *ych, *hhp;
    __half *win, *wout, *wofc1, *wofc2, *wafc1, *wafc2, *wmfc, *wmpj;
    cudaGetSymbolAddress((void**)&x1,   g_x1);
    cudaGetSymbolAddress((void**)&x2,   g_x2);
    cudaGetSymbolAddress((void**)&off2h,h_off2);
    cudaGetSymbolAddress((void**)&y2h,  h_y2);
    cudaGetSymbolAddress((void**)&qkvh, h_qkv);
    cudaGetSymbolAddress((void**)&lnh,  h_ln);
    cudaGetSymbolAddress((void**)&attnh,h_attn);
    cudaGetSymbolAddress((void**)&x1h,  h_x1);
    cudaGetSymbolAddress((void**)&diffh,h_diff);
    cudaGetSymbolAddress((void**)&off1h,h_off1);
    cudaGetSymbolAddress((void**)&offch,h_offc);
    cudaGetSymbolAddress((void**)&y1h,  h_y1);
    cudaGetSymbolAddress((void**)&ych,  h_yc);
    cudaGetSymbolAddress((void**)&hhp,  h_h);
    cudaGetSymbolAddress((void**)&win,  wh_in);
    cudaGetSymbolAddress((void**)&wout, wh_out);
    cudaGetSymbolAddress((void**)&wofc1,wh_ofc1);
    cudaGetSymbolAddress((void**)&wofc2,wh_ofc2);
    cudaGetSymbolAddress((void**)&wafc1,wh_afc1);
    cudaGetSymbolAddress((void**)&wafc2,wh_afc2);
    cudaGetSymbolAddress((void**)&wmfc, wh_mfc);
    cudaGetSymbolAddress((void**)&wmpj, wh_mpj);

    cudaFuncSetAttribute(attn_mma, cudaFuncAttributeMaxDynamicSharedMemorySize, ATTN_SMEM);
    cudaFuncSetAttribute(gemm16<1>, cudaFuncAttributeMaxDynamicSharedMemorySize, GEMM_SMEM);
    cudaFuncSetAttribute(gemm16<2>, cudaFuncAttributeMaxDynamicSharedMemorySize, GEMM_SMEM);
    cudaFuncSetAttribute(gemm16<3>, cudaFuncAttributeMaxDynamicSharedMemorySize, GEMM_SMEM);
    cudaFuncSetAttribute(gemm16<4>, cudaFuncAttributeMaxDynamicSharedMemorySize, GEMM_SMEM);
    cudaFuncSetAttribute(gemm16_dual<4>, cudaFuncAttributeMaxDynamicSharedMemorySize, GEMM_SMEM);

    const int EW = 256;
    const int gy_full = (MROWS + GBM - 1) / GBM;  // 129

    // 1) all weight conversions in ONE launch
    {
        F2HArgs a;
        a.src[0] = w_in;       a.dst[0] = win;   a.n4[0] = 3*DMODEL*DMODEL/4;
        a.src[1] = w_out;      a.dst[1] = wout;  a.n4[1] = DMODEL*DMODEL/4;
        a.src[2] = mlp_fc_w;   a.dst[2] = wmfc;  a.n4[2] = 4*DMODEL*DMODEL/4;
        a.src[3] = mlp_proj_w; a.dst[3] = wmpj;  a.n4[3] = 4*DMODEL*DMODEL/4;
        a.src[4] = o_fc1_w;    a.dst[4] = wofc1; a.n4[4] = CA*DMODEL/4;
        a.src[5] = o_fc2_w;    a.dst[5] = wofc2; a.n4[5] = DMODEL*CA/4;
        a.src[6] = a_fc1_w;    a.dst[6] = wafc1; a.n4[6] = CA*DMODEL/4;
        a.src[7] = a_fc2_w;    a.dst[7] = wafc2; a.n4[7] = DMODEL*CA/4;
        int tot = 0;
        for (int t = 0; t < 8; t++) tot += a.n4[t];
        f2h_oct<<<(tot + 255)/256, 256>>>(a);
    }

    // 2) ln1
    ln_kernel<<<MROWS, 256>>>(x, ln1_g, ln1_b, lnh);
    // 3) qkv (fp16 out)
    gemm16<4><<<dim3(3*DMODEL/GBN, gy_full), 256, GEMM_SMEM>>>(lnh, win, b_in, nullptr, nullptr, qkvh, MROWS, 3*DMODEL, DMODEL);
    // 4) attention (2 CTAs/head) — profiled slot
    attn_mma<<<BT * NHEAD * 2, AT_THREADS, ATTN_SMEM>>>(qkvh, attnh);
    // 5) out-proj + residual (fp32 + fp16 dual)
    gemm16<1><<<dim3(DMODEL/GBN, gy_full), 256, GEMM_SMEM>>>(attnh, wout, b_out, x, x1, x1h, MROWS, DMODEL, DMODEL);
    // 6) temporal diff (fp16 in/out)
    diff_kernel<<<(MOFF*DMODEL/4 + EW - 1)/EW, EW>>>(x1h, diffh);
    // 7) BOTH fc1 GEMMs in one launch, fp16 out
    gemm16_dual<4><<<dim3(CA/GBN, gy_full, 2), 256, GEMM_SMEM>>>(
        diffh, wofc1, o_fc1_b, nullptr, off1h, MOFF,
        x1h,   wafc1, a_fc1_b, nullptr, y1h,   MROWS, CA, DMODEL);
    // 8) BOTH depthwise convs in one launch
    conv_merged<<<((MOFF + MROWS)*CA + EW - 1)/EW, EW>>>(
        off1h, o_conv_w, o_conv_b, offch, y1h, a_conv_w, a_conv_b, ych);
    // 9) BOTH fc2 GEMMs in one launch, fp16 out
    gemm16_dual<4><<<dim3(DMODEL/GBN, gy_full, 2), 256, GEMM_SMEM>>>(
        offch, wofc2, o_fc2_b, nullptr, off2h, MOFF,
        ych,   wafc2, a_fc2_b, nullptr, y2h,   MROWS, DMODEL, CA);
    // 10) fused combine + ln2 (fp16 adapter inputs)
    combine_ln_kernel<<<MROWS, 256>>>(x1, y2h, off2h, ln2_g, ln2_b, x2, lnh);
    // 11) MLP fc + QuickGELU
    gemm16<2><<<dim3(4*DMODEL/GBN, gy_full), 256, GEMM_SMEM>>>(lnh, wmfc, mlp_fc_b, nullptr, nullptr, hhp, MROWS, 4*DMODEL, DMODEL);
    // 12) MLP proj + residual -> output
    gemm16<3><<<dim3(DMODEL/GBN, gy_full), 256, GEMM_SMEM>>>(hhp, wmpj, mlp_proj_b, x2, outp, nullptr, MROWS, DMODEL, 4*DMODEL);
}

// round 11
// speedup vs baseline: 1.0208x; 1.0208x over previous
#include <cuda_runtime.h>
#include <cuda_fp16.h>
#include <cstdint>

typedef unsigned int u32;

// ---------------------------------------------------------------------------
// Problem constants
// ---------------------------------------------------------------------------
#define DMODEL 1024
#define NHEAD  16
#define HDIM   64
#define CA     384
#define TT     16
#define BB     4
#define LL     257
#define BT     (BB*TT)            // 64
#define MROWS  (BT*LL)            // 16448
#define MOFF   (BT*(LL-1))        // 16384

// ---------------------------------------------------------------------------
// Scratch (static __device__ arrays; no dynamic allocation allowed)
// ---------------------------------------------------------------------------
__device__ float  g_x1  [(size_t)MROWS*DMODEL];
__device__ float  g_x2  [(size_t)MROWS*DMODEL];
__device__ __half h_off2[(size_t)MOFF*DMODEL];
__device__ __half h_y2  [(size_t)MROWS*DMODEL];
__device__ __half h_qkv [(size_t)MROWS*3*DMODEL];
__device__ __half h_ln  [(size_t)MROWS*DMODEL];
__device__ __half h_attn[(size_t)MROWS*DMODEL];
__device__ __half h_x1  [(size_t)MROWS*DMODEL];
__device__ __half h_diff[(size_t)MOFF*DMODEL];
__device__ __half h_off1[(size_t)MOFF*CA];
__device__ __half h_offc[(size_t)MOFF*CA];
__device__ __half h_y1  [(size_t)MROWS*CA];
__device__ __half h_yc  [(size_t)MROWS*CA];
__device__ __half h_h   [(size_t)MROWS*4*DMODEL];
__device__ __half wh_in  [3*DMODEL*DMODEL];
__device__ __half wh_out [DMODEL*DMODEL];
__device__ __half wh_ofc1[CA*DMODEL];
__device__ __half wh_ofc2[DMODEL*CA];
__device__ __half wh_afc1[CA*DMODEL];
__device__ __half wh_afc2[DMODEL*CA];
__device__ __half wh_mfc [4*DMODEL*DMODEL];
__device__ __half wh_mpj [DMODEL*4*DMODEL];

// ---------------------------------------------------------------------------
// helpers
// ---------------------------------------------------------------------------
__device__ __forceinline__ u32 smem_u32(const void* p) {
    u32 a;
    asm("{ .reg .u64 t; cvta.to.shared.u64 t, %1; cvt.u32.u64 %0, t; }"
        : "=r"(a) : "l"(p));
    return a;
}

__device__ __forceinline__ void ldmx4(u32& r0, u32& r1, u32& r2, u32& r3, u32 addr) {
    asm volatile("ldmatrix.sync.aligned.m8n8.x4.shared.b16 {%0,%1,%2,%3}, [%4];"
                 : "=r"(r0), "=r"(r1), "=r"(r2), "=r"(r3) : "r"(addr));
}

__device__ __forceinline__ void mma16816(float* c, u32 a0, u32 a1, u32 a2, u32 a3,
                                         u32 b0, u32 b1) {
    asm volatile(
        "mma.sync.aligned.m16n8k16.row.col.f32.f16.f16.f32 "
        "{%0,%1,%2,%3}, {%4,%5,%6,%7}, {%8,%9}, {%0,%1,%2,%3};\n"
        : "+f"(c[0]), "+f"(c[1]), "+f"(c[2]), "+f"(c[3])
        : "r"(a0), "r"(a1), "r"(a2), "r"(a3), "r"(b0), "r"(b1));
}

__device__ __forceinline__ u32 h2u(__half2 v) {
    return *reinterpret_cast<u32*>(&v);
}

// exp2 via degree-6 poly (rel err ~1e-5), FMA pipe only (no MUFU)
__device__ __forceinline__ float exp2p(float y) {
    y = fminf(fmaxf(y, -120.f), 88.f);
    int n = __float2int_rd(y);
    float f = y - (float)n;
    float p = 1.54035304e-4f;
    p = fmaf(p, f, 1.33335581e-3f);
    p = fmaf(p, f, 9.61812910e-3f);
    p = fmaf(p, f, 5.55041087e-2f);
    p = fmaf(p, f, 2.40226507e-1f);
    p = fmaf(p, f, 6.93147181e-1f);
    p = fmaf(p, f, 1.0f);
    return __int_as_float((n + 127) << 23) * p;
}

// ---------------------------------------------------------------------------
// fp32 -> fp16 weight conversion: ALL 8 weight tensors in ONE launch
// ---------------------------------------------------------------------------
struct F2HArgs {
    const float* src[8];
    __half*      dst[8];
    int          n4[8];
};

__global__ void f2h_oct(F2HArgs args)
{
    int i = blockIdx.x * blockDim.x + threadIdx.x;
    int j = i;
#pragma unroll
    for (int t = 0; t < 8; t++) {
        if (j < args.n4[t]) {
            float4 v = *(const float4*)(args.src[t] + (size_t)j * 4);
            __half2* o = (__half2*)(args.dst[t] + (size_t)j * 4);
            o[0] = __floats2half2_rn(v.x, v.y);
            o[1] = __floats2half2_rn(v.z, v.w);
            return;
        }
        j -= args.n4[t];
    }
}

// ---------------------------------------------------------------------------
// LayerNorm: one block per row, fp16 output
// ---------------------------------------------------------------------------
__global__ __launch_bounds__(256) void ln_kernel(
    const float* __restrict__ x, const float* __restrict__ gw,
    const float* __restrict__ bw, __half* __restrict__ y)
{
    __shared__ float red0[8], red1[8];
    const int row = blockIdx.x;
    const int tid = threadIdx.x;
    const float* xr = x + (size_t)row * DMODEL;
    float v[4];
    float s = 0.f, s2 = 0.f;
#pragma unroll
    for (int i = 0; i < 4; i++) {
        v[i] = xr[tid + i * 256];
        s += v[i];
        s2 += v[i] * v[i];
    }
#pragma unroll
    for (int o = 16; o > 0; o >>= 1) {
        s  += __shfl_xor_sync(0xffffffffu, s,  o);
        s2 += __shfl_xor_sync(0xffffffffu, s2, o);
    }
    if ((tid & 31) == 0) { red0[tid >> 5] = s; red1[tid >> 5] = s2; }
    __syncthreads();
    if (tid < 32) {
        float a  = (tid < 8) ? red0[tid] : 0.f;
        float a2 = (tid < 8) ? red1[tid] : 0.f;
#pragma unroll
        for (int o = 4; o > 0; o >>= 1) {
            a  += __shfl_xor_sync(0xffffffffu, a,  o);
            a2 += __shfl_xor_sync(0xffffffffu, a2, o);
        }
        if (tid == 0) { red0[0] = a; red1[0] = a2; }
    }
    __syncthreads();
    const float mean = red0[0] * (1.f / DMODEL);
    const float var  = red1[0] * (1.f / DMODEL) - mean * mean;
    const float inv  = rsqrtf(var + 1e-5f);
    __half* yr = y + (size_t)row * DMODEL;
#pragma unroll
    for (int i = 0; i < 4; i++) {
        int d = tid + i * 256;
        yr[d] = __float2half_rn((v[i] - mean) * inv * gw[d] + bw[d]);
    }
}

// ---------------------------------------------------------------------------
// Fused combine + LayerNorm2: x2 = x1 + y2 + scatter(off2); lnh = LN(x2)
// ---------------------------------------------------------------------------
__global__ __launch_bounds__(256) void combine_ln_kernel(
    const float* __restrict__ x1, const __half* __restrict__ y2,
    const __half* __restrict__ off2,
    const float* __restrict__ gw, const float* __restrict__ bw,
    float* __restrict__ x2, __half* __restrict__ yln)
{
    __shared__ float red0[8], red1[8];
    const int row = blockIdx.x;
    const int l  = row % LL;
    const int bt = row / LL;
    const int tid = threadIdx.x;
    const size_t rb = (size_t)row * DMODEL;
    const __half* offr = (l > 0) ? off2 + ((size_t)(bt * 256 + l - 1)) * DMODEL : nullptr;

    float v[4];
    float s = 0.f, s2 = 0.f;
#pragma unroll
    for (int i = 0; i < 4; i++) {
        int d = tid + i * 256;
        float a = x1[rb + d] + __half2float(y2[rb + d]);
        if (offr) a += __half2float(offr[d]);
        v[i] = a;
        x2[rb + d] = a;
        s += a;
        s2 += a * a;
    }
#pragma unroll
    for (int o = 16; o > 0; o >>= 1) {
        s  += __shfl_xor_sync(0xffffffffu, s,  o);
        s2 += __shfl_xor_sync(0xffffffffu, s2, o);
    }
    if ((tid & 31) == 0) { red0[tid >> 5] = s; red1[tid >> 5] = s2; }
    __syncthreads();
    if (tid < 32) {
        float a  = (tid < 8) ? red0[tid] : 0.f;
        float a2 = (tid < 8) ? red1[tid] : 0.f;
#pragma unroll
        for (int o = 4; o > 0; o >>= 1) {
            a  += __shfl_xor_sync(0xffffffffu, a,  o);
            a2 += __shfl_xor_sync(0xffffffffu, a2, o);
        }
        if (tid == 0) { red0[0] = a; red1[0] = a2; }
    }
    __syncthreads();
    const float mean = red0[0] * (1.f / DMODEL);
    const float var  = red1[0] * (1.f / DMODEL) - mean * mean;
    const float inv  = rsqrtf(var + 1e-5f);
    __half* yr = yln + rb;
#pragma unroll
    for (int i = 0; i < 4; i++) {
        int d = tid + i * 256;
        yr[d] = __float2half_rn((v[i] - mean) * inv * gw[d] + bw[d]);
    }
}

// ---------------------------------------------------------------------------
// Pipelined fp16 GEMM body (proven)
// EPI: 0 bias->f32 | 1 bias+res->f32+f16 | 2 bias+gelu->f16 | 3 bias+res->f32
//      4 bias->f16 only
// ---------------------------------------------------------------------------
#define GBM 128
#define GBN 128
#define GBK 64
#define STG_HALVES (128*64)
#define GEMM_SMEM  (3 * 2 * STG_HALVES * 2)
#define GELU_C (-2.4553766f)   /* -1.702 * log2(e) */

__device__ __forceinline__ void gemm_stage_load(
    const __half* __restrict__ A, const __half* __restrict__ W,
    int M, int K, int m0, int n0, int kt, u32 sA, u32 sB, int tid)
{
#pragma unroll
    for (int i = 0; i < 4; i++) {
        int cid = tid + i * 256;
        int row = cid >> 3, c = cid & 7;
        int sw  = ((c ^ (row & 7)) << 3);
        const __half* srcA = A + (size_t)(m0 + row) * K + kt * GBK + c * 8;
        u32 dA = sA + (u32)(row * 64 + sw) * 2;
        int szA = (m0 + row < M) ? 16 : 0;
        asm volatile("cp.async.cg.shared.global [%0], [%1], 16, %2;\n"
                     :: "r"(dA), "l"(srcA), "r"(szA));
        const __half* srcB = W + (size_t)(n0 + row) * K + kt * GBK + c * 8;
        u32 dB = sB + (u32)(row * 64 + sw) * 2;
        asm volatile("cp.async.cg.shared.global [%0], [%1], 16, 16;\n"
                     :: "r"(dB), "l"(srcB));
    }
    asm volatile("cp.async.commit_group;\n");
}

template <int EPI>
__device__ __forceinline__ void gemm_body(
    const __half* __restrict__ A, const __half* __restrict__ W,
    const float* __restrict__ bias, const float* __restrict__ res,
    float* __restrict__ C, __half* __restrict__ Ch,
    int M, int N, int K)
{
    extern __shared__ __half smh[];
    const u32 sbase = smem_u32(smh);

    const int tid    = threadIdx.x;
    const int lane   = tid & 31;
    const int wid    = tid >> 5;
    const int warp_m = wid & 3;
    const int warp_n = wid >> 2;
    const int m0 = blockIdx.y * GBM;
    const int n0 = blockIdx.x * GBN;
    const int mIdx = lane >> 3;
    const int rIn  = lane & 7;

    float acc[2][8][4];
#pragma unroll
    for (int i = 0; i < 2; i++)
#pragma unroll
        for (int j = 0; j < 8; j++)
#pragma unroll
            for (int k = 0; k < 4; k++) acc[i][j][k] = 0.f;

    const int ktiles = K / GBK;

    gemm_stage_load(A, W, M, K, m0, n0, 0, sbase, sbase + 3u*STG_HALVES*2, tid);
    gemm_stage_load(A, W, M, K, m0, n0, 1, sbase + 1u*STG_HALVES*2, sbase + 4u*STG_HALVES*2, tid);

    for (int kt = 0; kt < ktiles; kt++) {
        asm volatile("cp.async.wait_group 1;\n" ::: "memory");
        __syncthreads();

        if (kt + 2 < ktiles) {
            int slot = (kt + 2) % 3;
            gemm_stage_load(A, W, M, K, m0, n0, kt + 2,
                            sbase + (u32)slot * STG_HALVES * 2,
                            sbase + (u32)(3 + slot) * STG_HALVES * 2, tid);
        } else {
            asm volatile("cp.async.commit_group;\n");
        }

        const int slot = kt % 3;
        const u32 sA = sbase + (u32)slot * STG_HALVES * 2;
        const u32 sB = sbase + (u32)(3 + slot) * STG_HALVES * 2;

#pragma unroll
        for (int ks = 0; ks < 4; ks++) {
            u32 a00, a01, a02, a03, a10, a11, a12, a13;
            {
                int row   = warp_m * 32 + (mIdx & 1) * 8 + rIn;
                int chunk = ks * 2 + (mIdx >> 1);
                u32 ad0 = sA + (u32)(row * 64 + ((chunk ^ (row & 7)) << 3)) * 2;
                ldmx4(a00, a01, a02, a03, ad0);
                int row1 = row + 16;
                u32 ad1 = sA + (u32)(row1 * 64 + ((chunk ^ (row1 & 7)) << 3)) * 2;
                ldmx4(a10, a11, a12, a13, ad1);
            }
#pragma unroll
            for (int j = 0; j < 4; j++) {
                int nrow  = warp_n * 64 + j * 16 + (mIdx >> 1) * 8 + rIn;
                int chunk = ks * 2 + (mIdx & 1);
                u32 badr = sB + (u32)(nrow * 64 + ((chunk ^ (nrow & 7)) << 3)) * 2;
                u32 b0, b1, b2, b3;
                ldmx4(b0, b1, b2, b3, badr);
                mma16816(acc[0][2*j],   a00, a01, a02, a03, b0, b1);
                mma16816(acc[0][2*j+1], a00, a01, a02, a03, b2, b3);
                mma16816(acc[1][2*j],   a10, a11, a12, a13, b0, b1);
                mma16816(acc[1][2*j+1], a10, a11, a12, a13, b2, b3);
            }
        }
        // no trailing sync needed with 3-deep ring
    }

    const int g  = lane >> 2;
    const int tg = lane & 3;
#pragma unroll
    for (int mi = 0; mi < 2; mi++) {
#pragma unroll
        for (int ni = 0; ni < 8; ni++) {
            const int col = n0 + warp_n * 64 + ni * 8 + tg * 2;
            const float bc0 = bias[col], bc1 = bias[col + 1];
#pragma unroll
            for (int hh = 0; hh < 2; hh++) {
                int row = m0 + warp_m * 32 + mi * 16 + g + hh * 8;
                if (row < M) {
                    float v0 = acc[mi][ni][hh * 2 + 0] + bc0;
                    float v1 = acc[mi][ni][hh * 2 + 1] + bc1;
                    if (EPI == 2) {
                        v0 = __fdividef(v0, 1.f + exp2p(GELU_C * v0));
                        v1 = __fdividef(v1, 1.f + exp2p(GELU_C * v1));
                        *(__half2*)(Ch + (size_t)row * N + col) = __floats2half2_rn(v0, v1);
                    } else if (EPI == 4) {
                        *(__half2*)(Ch + (size_t)row * N + col) = __floats2half2_rn(v0, v1);
                    } else {
                        if (EPI == 1 || EPI == 3) {
                            const float2 rr = *(const float2*)(res + (size_t)row * N + col);
                            v0 += rr.x; v1 += rr.y;
                        }
                        *(float2*)(C + (size_t)row * N + col) = make_float2(v0, v1);
                        if (EPI == 1)
                            *(__half2*)(Ch + (size_t)row * N + col) = __floats2half2_rn(v0, v1);
                    }
                }
            }
        }
    }
}

template <int EPI>
__global__ __launch_bounds__(256, 2) void gemm16(
    const __half* __restrict__ A, const __half* __restrict__ W,
    const float* __restrict__ bias, const float* __restrict__ res,
    float* __restrict__ C, __half* __restrict__ Ch,
    int M, int N, int K)
{
    gemm_body<EPI>(A, W, bias, res, C, Ch, M, N, K);
}

// dual-problem GEMM (fills partial waves of small grids)
template <int EPI>
__global__ __launch_bounds__(256, 2) void gemm16_dual(
    const __half* __restrict__ A0, const __half* __restrict__ W0,
    const float* __restrict__ b0, float* __restrict__ C0, __half* __restrict__ Ch0, int M0,
    const __half* __restrict__ A1, const __half* __restrict__ W1,
    const float* __restrict__ b1, float* __restrict__ C1, __half* __restrict__ Ch1, int M1,
    int N, int K)
{
    if (blockIdx.z == 0)
        gemm_body<EPI>(A0, W0, b0, nullptr, C0, Ch0, M0, N, K);
    else
        gemm_body<EPI>(A1, W1, b1, nullptr, C1, Ch1, M1, N, K);
}

// ---------------------------------------------------------------------------
// Tensor-core flash attention (round-9 proven): one CTA per (bt, head),
// 544 threads = 17 warps, one 16-query tile per warp.
// ---------------------------------------------------------------------------
#define ATT_THREADS 544
#define QK_ROW 72
#define VT_ROW 280
#define LPAD   272
#define NKT    17
#define SK_OFF  (LPAD*QK_ROW)
#define SVT_OFF (2*LPAD*QK_ROW)
#define ATTN_SMEM ((SVT_OFF + HDIM*VT_ROW) * 2)
#define QSC 0.1803368801111244f   /* hd^-0.5 * log2(e) */

__global__ __launch_bounds__(ATT_THREADS, 1) void attn_mma(
    const __half* __restrict__ qkvh, __half* __restrict__ out)
{
    extern __shared__ __half smA[];
    __half* sQh  = smA;
    __half* sKh  = smA + SK_OFF;
    __half* sVth = smA + SVT_OFF;
    const u32 sQ  = smem_u32(smA);
    const u32 sK  = sQ + SK_OFF * 2;
    const u32 sVt = sQ + SVT_OFF * 2;

    const int bt = blockIdx.x >> 4;
    const int h  = blockIdx.x & 15;
    const int tid = threadIdx.x;
    const __half* base = qkvh + (size_t)bt * LL * (3 * DMODEL) + h * HDIM;

    for (int i = tid; i < LL * 16; i += ATT_THREADS) {
        int l = i >> 4, d4 = i & 15;
        const __half* p = base + (size_t)l * (3 * DMODEL) + d4 * 4;
        uint2 qr = *(const uint2*)(p);
        uint2 kr = *(const uint2*)(p + DMODEL);
        uint2 vr = *(const uint2*)(p + 2 * DMODEL);
        float2 qa = __half22float2(*(__half2*)&qr.x);
        float2 qb = __half22float2(*(__half2*)&qr.y);
        __half2* qd = (__half2*)(sQh + l * QK_ROW + d4 * 4);
        qd[0] = __floats2half2_rn(qa.x * QSC, qa.y * QSC);
        qd[1] = __floats2half2_rn(qb.x * QSC, qb.y * QSC);
        *(uint2*)(sKh + l * QK_ROW + d4 * 4) = kr;
        __half2 v01 = *(__half2*)&vr.x;
        __half2 v23 = *(__half2*)&vr.y;
        int d = d4 * 4;
        sVth[(d + 0) * VT_ROW + l] = __low2half(v01);
        sVth[(d + 1) * VT_ROW + l] = __high2half(v01);
        sVth[(d + 2) * VT_ROW + l] = __low2half(v23);
        sVth[(d + 3) * VT_ROW + l] = __high2half(v23);
    }
    for (int i = tid; i < 15 * HDIM; i += ATT_THREADS) {
        int l = LL + (i >> 6);
        int d = i & 63;
        __half z = __float2half(0.f);
        sQh[l * QK_ROW + d] = z;
        sKh[l * QK_ROW + d] = z;
        sVth[d * VT_ROW + l] = z;
    }
    __syncthreads();

    const int wid  = tid >> 5;
    const int lane = tid & 31;
    const int g    = lane >> 2;
    const int tg   = lane & 3;
    const int mIdx = lane >> 3;
    const int rIn  = lane & 7;
    const int qt   = wid;

    u32 aQ[4][4];
#pragma unroll
    for (int kc = 0; kc < 4; kc++) {
        int row   = qt * 16 + (mIdx & 1) * 8 + rIn;
        int chunk = kc * 2 + (mIdx >> 1);
        ldmx4(aQ[kc][0], aQ[kc][1], aQ[kc][2], aQ[kc][3],
              sQ + (u32)(row * QK_ROW + chunk * 8) * 2);
    }

    float m0 = -1e30f, m1 = -1e30f, l0 = 0.f, l1 = 0.f;
    float oacc[8][4];
#pragma unroll
    for (int n = 0; n < 8; n++)
#pragma unroll
        for (int j = 0; j < 4; j++) oacc[n][j] = 0.f;

    for (int kt = 0; kt < NKT; kt++) {
        float sf[2][4];
#pragma unroll
        for (int j = 0; j < 4; j++) { sf[0][j] = 0.f; sf[1][j] = 0.f; }
#pragma unroll
        for (int kc = 0; kc < 4; kc++) {
            int nrow  = kt * 16 + (mIdx >> 1) * 8 + rIn;
            int chunk = kc * 2 + (mIdx & 1);
            u32 b0, b1, b2, b3;
            ldmx4(b0, b1, b2, b3, sK + (u32)(nrow * QK_ROW + chunk * 8) * 2);
            mma16816(sf[0], aQ[kc][0], aQ[kc][1], aQ[kc][2], aQ[kc][3], b0, b1);
            mma16816(sf[1], aQ[kc][0], aQ[kc][1], aQ[kc][2], aQ[kc][3], b2, b3);
        }
        if (kt == 16) {
            bool v0 = (tg == 0);
            sf[0][0] = v0 ? sf[0][0] : -1e30f;
            sf[0][2] = v0 ? sf[0][2] : -1e30f;
            sf[0][1] = -1e30f; sf[0][3] = -1e30f;
            sf[1][0] = -1e30f; sf[1][1] = -1e30f;
            sf[1][2] = -1e30f; sf[1][3] = -1e30f;
        }
        float tm0 = fmaxf(fmaxf(sf[0][0], sf[0][1]), fmaxf(sf[1][0], sf[1][1]));
        float tm1 = fmaxf(fmaxf(sf[0][2], sf[0][3]), fmaxf(sf[1][2], sf[1][3]));
        tm0 = fmaxf(tm0, __shfl_xor_sync(0xffffffffu, tm0, 1));
        tm0 = fmaxf(tm0, __shfl_xor_sync(0xffffffffu, tm0, 2));
        tm1 = fmaxf(tm1, __shfl_xor_sync(0xffffffffu, tm1, 1));
        tm1 = fmaxf(tm1, __shfl_xor_sync(0xffffffffu, tm1, 2));
        if (tm0 > m0) {
            float c = exp2p(m0 - tm0);
            m0 = tm0; l0 *= c;
#pragma unroll
            for (int n = 0; n < 8; n++) { oacc[n][0] *= c; oacc[n][1] *= c; }
        }
        if (tm1 > m1) {
            float c = exp2p(m1 - tm1);
            m1 = tm1; l1 *= c;
#pragma unroll
            for (int n = 0; n < 8; n++) { oacc[n][2] *= c; oacc[n][3] *= c; }
        }
        float p00 = exp2p(sf[0][0] - m0), p01 = exp2p(sf[0][1] - m0);
        float p02 = exp2p(sf[1][0] - m0), p03 = exp2p(sf[1][1] - m0);
        float p10 = exp2p(sf[0][2] - m1), p11 = exp2p(sf[0][3] - m1);
        float p12 = exp2p(sf[1][2] - m1), p13 = exp2p(sf[1][3] - m1);
        l0 += (p00 + p01) + (p02 + p03);
        l1 += (p10 + p11) + (p12 + p13);
        u32 aP0 = h2u(__floats2half2_rn(p00, p01));
        u32 aP1 = h2u(__floats2half2_rn(p10, p11));
        u32 aP2 = h2u(__floats2half2_rn(p02, p03));
        u32 aP3 = h2u(__floats2half2_rn(p12, p13));
#pragma unroll
        for (int np = 0; np < 4; np++) {
            int nrow  = np * 16 + (mIdx >> 1) * 8 + rIn;
            int chunk = kt * 2 + (mIdx & 1);
            u32 b0, b1, b2, b3;
            ldmx4(b0, b1, b2, b3, sVt + (u32)(nrow * VT_ROW + chunk * 8) * 2);
            mma16816(oacc[2*np],     aP0, aP1, aP2, aP3, b0, b1);
            mma16816(oacc[2*np + 1], aP0, aP1, aP2, aP3, b2, b3);
        }
    }
    l0 += __shfl_xor_sync(0xffffffffu, l0, 1);
    l0 += __shfl_xor_sync(0xffffffffu, l0, 2);
    l1 += __shfl_xor_sync(0xffffffffu, l1, 1);
    l1 += __shfl_xor_sync(0xffffffffu, l1, 2);
    float inv0 = 1.f / l0, inv1 = 1.f / l1;
    int r0 = qt * 16 + g;
    int r1 = r0 + 8;
    if (r0 < LL) {
        __half2* o = (__half2*)(out + ((size_t)bt * LL + r0) * DMODEL + h * HDIM);
#pragma unroll
        for (int n = 0; n < 8; n++)
            o[(n * 8 + tg * 2) >> 1] = __floats2half2_rn(oacc[n][0] * inv0, oacc[n][1] * inv0);
    }
    if (r1 < LL) {
        __half2* o = (__half2*)(out + ((size_t)bt * LL + r1) * DMODEL + h * HDIM);
#pragma unroll
        for (int n = 0; n < 8; n++)
            o[(n * 8 + tg * 2) >> 1] = __floats2half2_rn(oacc[n][2] * inv1, oacc[n][3] * inv1);
    }
}

// ---------------------------------------------------------------------------
// Elementwise / conv kernels
// ---------------------------------------------------------------------------
// temporal diff of patch tokens, fp16 in / fp16 out
__global__ void diff_kernel(const __half* __restrict__ x1h, __half* __restrict__ diff)
{
    int i = blockIdx.x * blockDim.x + threadIdx.x;   // 4 elems per thread
    if (i >= MOFF * DMODEL / 4) return;
    int r = i >> 8;
    int p = r & 255;
    int f = r >> 8;
    int t = f & (TT - 1);
    size_t cur = ((size_t)f * LL + (p + 1)) * DMODEL + (size_t)(i & 255) * 4;
    uint2 v = *(const uint2*)(x1h + cur);
    uint2 pv = (t > 0) ? *(const uint2*)(x1h + cur - (size_t)LL * DMODEL) : v;
    __half2* o = (__half2*)(diff + (size_t)i * 4);
    o[0] = __hsub2(*(__half2*)&v.x, *(__half2*)&pv.x);
    o[1] = __hsub2(*(__half2*)&v.y, *(__half2*)&pv.y);
}

// merged depthwise convs (fp16 in/out)
__global__ void conv_merged(const __half* __restrict__ off1,
                            const float* __restrict__ ocw, const float* __restrict__ ocb,
                            __half* __restrict__ offc,
                            const __half* __restrict__ y1,
                            const float* __restrict__ acw, const float* __restrict__ acb,
                            __half* __restrict__ yc)
{
    int idx = blockIdx.x * blockDim.x + threadIdx.x;
    if (idx < MOFF * CA) {
        int c = idx % CA;
        int r = idx / CA;
        int p = r & 255;
        int n = r >> 8;
        int hh = p >> 4, ww = p & 15;
        float s = ocb[c];
#pragma unroll
        for (int dh = 0; dh < 3; dh++) {
            int h2 = hh + dh - 1;
            if (h2 < 0 || h2 > 15) continue;
#pragma unroll
            for (int dw = 0; dw < 3; dw++) {
                int w2 = ww + dw - 1;
                if (w2 < 0 || w2 > 15) continue;
                s += __half2float(off1[((size_t)(n * 256 + h2 * 16 + w2)) * CA + c])
                     * ocw[(dh * 3 + dw) * CA + c];
            }
        }
        offc[idx] = __float2half_rn(s);
    } else {
        int k = idx - MOFF * CA;
        if (k >= MROWS * CA) return;
        int c = k % CA;
        int row = k / CA;
        int l = row % LL;
        int bt = row / LL;
        int t = bt & (TT - 1);
        float s = acb[c];
#pragma unroll
        for (int dt = 0; dt < 3; dt++) {
            int tt = t + dt - 1;
            if (tt < 0 || tt >= TT) continue;
            s += __half2float(y1[((size_t)(bt + dt - 1) * LL + l) * CA + c]) * acw[dt * CA + c];
        }
        yc[k] = __float2half_rn(s);
    }
}

// ---------------------------------------------------------------------------
// Launch
// ---------------------------------------------------------------------------
extern "C" void kernel_launch(void* const* d_in, const int* in_sizes, int n_in,
                              void* d_out, int out_size)
{
    const float* x         = (const float*)d_in[0];
    const float* ln1_g     = (const float*)d_in[1];
    const float* ln1_b     = (const float*)d_in[2];
    const float* w_in      = (const float*)d_in[3];
    const float* b_in      = (const float*)d_in[4];
    const float* w_out     = (const float*)d_in[5];
    const float* b_out     = (const float*)d_in[6];
    const float* o_fc1_w   = (const float*)d_in[7];
    const float* o_fc1_b   = (const float*)d_in[8];
    const float* o_conv_w  = (const float*)d_in[9];
    const float* o_conv_b  = (const float*)d_in[10];
    const float* o_fc2_w   = (const float*)d_in[11];
    const float* o_fc2_b   = (const float*)d_in[12];
    const float* a_fc1_w   = (const float*)d_in[13];
    const float* a_fc1_b   = (const float*)d_in[14];
    const float* a_conv_w  = (const float*)d_in[15];
    const float* a_conv_b  = (const float*)d_in[16];
    const float* a_fc2_w   = (const float*)d_in[17];
    const float* a_fc2_b   = (const float*)d_in[18];
    const float* ln2_g     = (const float*)d_in[19];
    const float* ln2_b     = (const float*)d_in[20];
    const float* mlp_fc_w  = (const float*)d_in[21];
    const float* mlp_fc_b  = (const float*)d_in[22];
    const float* mlp_proj_w= (const float*)d_in[23];
    const float* mlp_proj_b= (const float*)d_in[24];
    float* outp = (float*)d_out;

    float *x1, *x2;
    __half *off2h, *y2h;
    __half *qkvh, *lnh, *attnh, *x1h, *diffh, *off1h, *offch, *y1h, *ych, *hhp;
    __half *win, *wout, *wofc1, *wofc2, *wafc1, *wafc2, *wmfc, *wmpj;
    cudaGetSymbolAddress((void**)&x1,   g_x1);
    cudaGetSymbolAddress((void**)&x2,   g_x2);
    cudaGetSymbolAddress((void**)&off2h,h_off2);
    cudaGetSymbolAddress((void**)&y2h,  h_y2);
    cudaGetSymbolAddress((void**)&qkvh, h_qkv);
    cudaGetSymbolAddress((void**)&lnh,  h_ln);
    cudaGetSymbolAddress((void**)&attnh,h_attn);
    cudaGetSymbolAddress((void**)&x1h,  h_x1);
    cudaGetSymbolAddress((void**)&diffh,h_diff);
    cudaGetSymbolAddress((void**)&off1h,h_off1);
    cudaGetSymbolAddress((void**)&offch,h_offc);
    cudaGetSymbolAddress((void**)&y1h,  h_y1);
    cudaGetSymbolAddress((void**)&ych,  h_yc);
    cudaGetSymbolAddress((void**)&hhp,  h_h);
    cudaGetSymbolAddress((void**)&win,  wh_in);
    cudaGetSymbolAddress((void**)&wout, wh_out);
    cudaGetSymbolAddress((void**)&wofc1,wh_ofc1);
    cudaGetSymbolAddress((void**)&wofc2,wh_ofc2);
    cudaGetSymbolAddress((void**)&wafc1,wh_afc1);
    cudaGetSymbolAddress((void**)&wafc2,wh_afc2);
    cudaGetSymbolAddress((void**)&wmfc, wh_mfc);
    cudaGetSymbolAddress((void**)&wmpj, wh_mpj);

    cudaFuncSetAttribute(attn_mma, cudaFuncAttributeMaxDynamicSharedMemorySize, ATTN_SMEM);
    cudaFuncSetAttribute(gemm16<1>, cudaFuncAttributeMaxDynamicSharedMemorySize, GEMM_SMEM);
    cudaFuncSetAttribute(gemm16<2>, cudaFuncAttributeMaxDynamicSharedMemorySize, GEMM_SMEM);
    cudaFuncSetAttribute(gemm16<3>, cudaFuncAttributeMaxDynamicSharedMemorySize, GEMM_SMEM);
    cudaFuncSetAttribute(gemm16<4>, cudaFuncAttributeMaxDynamicSharedMemorySize, GEMM_SMEM);
    cudaFuncSetAttribute(gemm16_dual<4>, cudaFuncAttributeMaxDynamicSharedMemorySize, GEMM_SMEM);

    const int EW = 256;
    const int gy_full = (MROWS + GBM - 1) / GBM;  // 129

    // 1) all weight conversions in ONE launch
    {
        F2HArgs a;
        a.src[0] = w_in;       a.dst[0] = win;   a.n4[0] = 3*DMODEL*DMODEL/4;
        a.src[1] = w_out;      a.dst[1] = wout;  a.n4[1] = DMODEL*DMODEL/4;
        a.src[2] = mlp_fc_w;   a.dst[2] = wmfc;  a.n4[2] = 4*DMODEL*DMODEL/4;
        a.src[3] = mlp_proj_w; a.dst[3] = wmpj;  a.n4[3] = 4*DMODEL*DMODEL/4;
        a.src[4] = o_fc1_w;    a.dst[4] = wofc1; a.n4[4] = CA*DMODEL/4;
        a.src[5] = o_fc2_w;    a.dst[5] = wofc2; a.n4[5] = DMODEL*CA/4;
        a.src[6] = a_fc1_w;    a.dst[6] = wafc1; a.n4[6] = CA*DMODEL/4;
        a.src[7] = a_fc2_w;    a.dst[7] = wafc2; a.n4[7] = DMODEL*CA/4;
        int tot = 0;
        for (int t = 0; t < 8; t++) tot += a.n4[t];
        f2h_oct<<<(tot + 255)/256, 256>>>(a);
    }

    // 2) ln1
    ln_kernel<<<MROWS, 256>>>(x, ln1_g, ln1_b, lnh);
    // 3) qkv (fp16 out)
    gemm16<4><<<dim3(3*DMODEL/GBN, gy_full), 256, GEMM_SMEM>>>(lnh, win, b_in, nullptr, nullptr, qkvh, MROWS, 3*DMODEL, DMODEL);
    // 4) attention (proven 17-warp kernel) — profiled slot
    attn_mma<<<BT * NHEAD, ATT_THREADS, ATTN_SMEM>>>(qkvh, attnh);
    // 5) out-proj + residual (fp32 + fp16 dual)
    gemm16<1><<<dim3(DMODEL/GBN, gy_full), 256, GEMM_SMEM>>>(attnh, wout, b_out, x, x1, x1h, MROWS, DMODEL, DMODEL);
    // 6) temporal diff (fp16 in/out)
    diff_kernel<<<(MOFF*DMODEL/4 + EW - 1)/EW, EW>>>(x1h, diffh);
    // 7) BOTH fc1 GEMMs in one launch, fp16 out
    gemm16_dual<4><<<dim3(CA/GBN, gy_full, 2), 256, GEMM_SMEM>>>(
        diffh, wofc1, o_fc1_b, nullptr, off1h, MOFF,
        x1h,   wafc1, a_fc1_b, nullptr, y1h,   MROWS, CA, DMODEL);
    // 8) BOTH depthwise convs in one launch
    conv_merged<<<((MOFF + MROWS)*CA + EW - 1)/EW, EW>>>(
        off1h, o_conv_w, o_conv_b, offch, y1h, a_conv_w, a_conv_b, ych);
    // 9) BOTH fc2 GEMMs in one launch, fp16 out
    gemm16_dual<4><<<dim3(DMODEL/GBN, gy_full, 2), 256, GEMM_SMEM>>>(
        offch, wofc2, o_fc2_b, nullptr, off2h, MOFF,
        ych,   wafc2, a_fc2_b, nullptr, y2h,   MROWS, DMODEL, CA);
    // 10) fused combine + ln2 (fp16 adapter inputs)
    combine_ln_kernel<<<MROWS, 256>>>(x1, y2h, off2h, ln2_g, ln2_b, x2, lnh);
    // 11) MLP fc + QuickGELU
    gemm16<2><<<dim3(4*DMODEL/GBN, gy_full), 256, GEMM_SMEM>>>(lnh, wmfc, mlp_fc_b, nullptr, nullptr, hhp, MROWS, 4*DMODEL, DMODEL);
    // 12) MLP proj + residual -> output
    gemm16<3><<<dim3(DMODEL/GBN, gy_full), 256, GEMM_SMEM>>>(hhp, wmpj, mlp_proj_b, x2, outp, nullptr, MROWS, DMODEL, 4*DMODEL);
}

// round 12
// speedup vs baseline: 1.0348x; 1.0137x over previous
#include <cuda_runtime.h>
#include <cuda_fp16.h>
#include <cstdint>

typedef unsigned int u32;

// ---------------------------------------------------------------------------
// Problem constants
// ---------------------------------------------------------------------------
#define DMODEL 1024
#define NHEAD  16
#define HDIM   64
#define CA     384
#define TT     16
#define BB     4
#define LL     257
#define BT     (BB*TT)            // 64
#define MROWS  (BT*LL)            // 16448
#define MOFF   (BT*(LL-1))        // 16384

// ---------------------------------------------------------------------------
// Scratch (static __device__ arrays; no dynamic allocation allowed)
// ---------------------------------------------------------------------------
__device__ __half h_x2  [(size_t)MROWS*DMODEL];
__device__ __half h_off2[(size_t)MOFF*DMODEL];
__device__ __half h_y2  [(size_t)MROWS*DMODEL];
__device__ __half h_qkv [(size_t)MROWS*3*DMODEL];
__device__ __half h_ln  [(size_t)MROWS*DMODEL];
__device__ __half h_attn[(size_t)MROWS*DMODEL];
__device__ __half h_x1  [(size_t)MROWS*DMODEL];
__device__ __half h_diff[(size_t)MOFF*DMODEL];
__device__ __half h_off1[(size_t)MOFF*CA];
__device__ __half h_offc[(size_t)MOFF*CA];
__device__ __half h_y1  [(size_t)MROWS*CA];
__device__ __half h_yc  [(size_t)MROWS*CA];
__device__ __half h_h   [(size_t)MROWS*4*DMODEL];
__device__ __half wh_in  [3*DMODEL*DMODEL];
__device__ __half wh_out [DMODEL*DMODEL];
__device__ __half wh_ofc1[CA*DMODEL];
__device__ __half wh_ofc2[DMODEL*CA];
__device__ __half wh_afc1[CA*DMODEL];
__device__ __half wh_afc2[DMODEL*CA];
__device__ __half wh_mfc [4*DMODEL*DMODEL];
__device__ __half wh_mpj [DMODEL*4*DMODEL];

// ---------------------------------------------------------------------------
// helpers
// ---------------------------------------------------------------------------
__device__ __forceinline__ u32 smem_u32(const void* p) {
    u32 a;
    asm("{ .reg .u64 t; cvta.to.shared.u64 t, %1; cvt.u32.u64 %0, t; }"
        : "=r"(a) : "l"(p));
    return a;
}

__device__ __forceinline__ void ldmx4(u32& r0, u32& r1, u32& r2, u32& r3, u32 addr) {
    asm volatile("ldmatrix.sync.aligned.m8n8.x4.shared.b16 {%0,%1,%2,%3}, [%4];"
                 : "=r"(r0), "=r"(r1), "=r"(r2), "=r"(r3) : "r"(addr));
}

__device__ __forceinline__ void mma16816(float* c, u32 a0, u32 a1, u32 a2, u32 a3,
                                         u32 b0, u32 b1) {
    asm volatile(
        "mma.sync.aligned.m16n8k16.row.col.f32.f16.f16.f32 "
        "{%0,%1,%2,%3}, {%4,%5,%6,%7}, {%8,%9}, {%0,%1,%2,%3};\n"
        : "+f"(c[0]), "+f"(c[1]), "+f"(c[2]), "+f"(c[3])
        : "r"(a0), "r"(a1), "r"(a2), "r"(a3), "r"(b0), "r"(b1));
}

__device__ __forceinline__ u32 h2u(__half2 v) {
    return *reinterpret_cast<u32*>(&v);
}

// exp2 via degree-6 poly (rel err ~1e-5), FMA pipe only (no MUFU)
__device__ __forceinline__ float exp2p(float y) {
    y = fminf(fmaxf(y, -120.f), 88.f);
    int n = __float2int_rd(y);
    float f = y - (float)n;
    float p = 1.54035304e-4f;
    p = fmaf(p, f, 1.33335581e-3f);
    p = fmaf(p, f, 9.61812910e-3f);
    p = fmaf(p, f, 5.55041087e-2f);
    p = fmaf(p, f, 2.40226507e-1f);
    p = fmaf(p, f, 6.93147181e-1f);
    p = fmaf(p, f, 1.0f);
    return __int_as_float((n + 127) << 23) * p;
}

// ---------------------------------------------------------------------------
// fp32 -> fp16 weight conversion: ALL 8 weight tensors in ONE launch
// ---------------------------------------------------------------------------
struct F2HArgs {
    const float* src[8];
    __half*      dst[8];
    int          n4[8];
};

__global__ void f2h_oct(F2HArgs args)
{
    int i = blockIdx.x * blockDim.x + threadIdx.x;
    int j = i;
#pragma unroll
    for (int t = 0; t < 8; t++) {
        if (j < args.n4[t]) {
            float4 v = *(const float4*)(args.src[t] + (size_t)j * 4);
            __half2* o = (__half2*)(args.dst[t] + (size_t)j * 4);
            o[0] = __floats2half2_rn(v.x, v.y);
            o[1] = __floats2half2_rn(v.z, v.w);
            return;
        }
        j -= args.n4[t];
    }
}

// ---------------------------------------------------------------------------
// LayerNorm: one block per row, fp16 output
// ---------------------------------------------------------------------------
__global__ __launch_bounds__(256) void ln_kernel(
    const float* __restrict__ x, const float* __restrict__ gw,
    const float* __restrict__ bw, __half* __restrict__ y)
{
    __shared__ float red0[8], red1[8];
    const int row = blockIdx.x;
    const int tid = threadIdx.x;
    const float* xr = x + (size_t)row * DMODEL;
    float v[4];
    float s = 0.f, s2 = 0.f;
#pragma unroll
    for (int i = 0; i < 4; i++) {
        v[i] = xr[tid + i * 256];
        s += v[i];
        s2 += v[i] * v[i];
    }
#pragma unroll
    for (int o = 16; o > 0; o >>= 1) {
        s  += __shfl_xor_sync(0xffffffffu, s,  o);
        s2 += __shfl_xor_sync(0xffffffffu, s2, o);
    }
    if ((tid & 31) == 0) { red0[tid >> 5] = s; red1[tid >> 5] = s2; }
    __syncthreads();
    if (tid < 32) {
        float a  = (tid < 8) ? red0[tid] : 0.f;
        float a2 = (tid < 8) ? red1[tid] : 0.f;
#pragma unroll
        for (int o = 4; o > 0; o >>= 1) {
            a  += __shfl_xor_sync(0xffffffffu, a,  o);
            a2 += __shfl_xor_sync(0xffffffffu, a2, o);
        }
        if (tid == 0) { red0[0] = a; red1[0] = a2; }
    }
    __syncthreads();
    const float mean = red0[0] * (1.f / DMODEL);
    const float var  = red1[0] * (1.f / DMODEL) - mean * mean;
    const float inv  = rsqrtf(var + 1e-5f);
    __half* yr = y + (size_t)row * DMODEL;
#pragma unroll
    for (int i = 0; i < 4; i++) {
        int d = tid + i * 256;
        yr[d] = __float2half_rn((v[i] - mean) * inv * gw[d] + bw[d]);
    }
}

// ---------------------------------------------------------------------------
// Fused combine + LayerNorm2 (all-fp16 residual stream):
// x2h = x1h + y2h + scatter(off2h);  lnh = LN(x2h)   (stats in fp32)
// ---------------------------------------------------------------------------
__global__ __launch_bounds__(256) void combine_ln_kernel(
    const __half* __restrict__ x1, const __half* __restrict__ y2,
    const __half* __restrict__ off2,
    const float* __restrict__ gw, const float* __restrict__ bw,
    __half* __restrict__ x2, __half* __restrict__ yln)
{
    __shared__ float red0[8], red1[8];
    const int row = blockIdx.x;
    const int l  = row % LL;
    const int bt = row / LL;
    const int tid = threadIdx.x;
    const size_t rb = (size_t)row * DMODEL;
    const __half* offr = (l > 0) ? off2 + ((size_t)(bt * 256 + l - 1)) * DMODEL : nullptr;

    float v[4];
    float s = 0.f, s2 = 0.f;
#pragma unroll
    for (int i = 0; i < 4; i++) {
        int d = tid + i * 256;
        float a = __half2float(x1[rb + d]) + __half2float(y2[rb + d]);
        if (offr) a += __half2float(offr[d]);
        v[i] = a;
        x2[rb + d] = __float2half_rn(a);
        s += a;
        s2 += a * a;
    }
#pragma unroll
    for (int o = 16; o > 0; o >>= 1) {
        s  += __shfl_xor_sync(0xffffffffu, s,  o);
        s2 += __shfl_xor_sync(0xffffffffu, s2, o);
    }
    if ((tid & 31) == 0) { red0[tid >> 5] = s; red1[tid >> 5] = s2; }
    __syncthreads();
    if (tid < 32) {
        float a  = (tid < 8) ? red0[tid] : 0.f;
        float a2 = (tid < 8) ? red1[tid] : 0.f;
#pragma unroll
        for (int o = 4; o > 0; o >>= 1) {
            a  += __shfl_xor_sync(0xffffffffu, a,  o);
            a2 += __shfl_xor_sync(0xffffffffu, a2, o);
        }
        if (tid == 0) { red0[0] = a; red1[0] = a2; }
    }
    __syncthreads();
    const float mean = red0[0] * (1.f / DMODEL);
    const float var  = red1[0] * (1.f / DMODEL) - mean * mean;
    const float inv  = rsqrtf(var + 1e-5f);
    __half* yr = yln + rb;
#pragma unroll
    for (int i = 0; i < 4; i++) {
        int d = tid + i * 256;
        yr[d] = __float2half_rn((v[i] - mean) * inv * gw[d] + bw[d]);
    }
}

// ---------------------------------------------------------------------------
// Pipelined fp16 GEMM body (proven)
// EPI: 2 bias+gelu->f16 | 4 bias->f16 | 5 bias+res(f32)->f16 | 6 bias+res(f16)->f32
// ---------------------------------------------------------------------------
#define GBM 128
#define GBN 128
#define GBK 64
#define STG_HALVES (128*64)
#define GEMM_SMEM  (3 * 2 * STG_HALVES * 2)
#define GELU_C (-2.4553766f)   /* -1.702 * log2(e) */

__device__ __forceinline__ void gemm_stage_load(
    const __half* __restrict__ A, const __half* __restrict__ W,
    int M, int K, int m0, int n0, int kt, u32 sA, u32 sB, int tid)
{
#pragma unroll
    for (int i = 0; i < 4; i++) {
        int cid = tid + i * 256;
        int row = cid >> 3, c = cid & 7;
        int sw  = ((c ^ (row & 7)) << 3);
        const __half* srcA = A + (size_t)(m0 + row) * K + kt * GBK + c * 8;
        u32 dA = sA + (u32)(row * 64 + sw) * 2;
        int szA = (m0 + row < M) ? 16 : 0;
        asm volatile("cp.async.cg.shared.global [%0], [%1], 16, %2;\n"
                     :: "r"(dA), "l"(srcA), "r"(szA));
        const __half* srcB = W + (size_t)(n0 + row) * K + kt * GBK + c * 8;
        u32 dB = sB + (u32)(row * 64 + sw) * 2;
        asm volatile("cp.async.cg.shared.global [%0], [%1], 16, 16;\n"
                     :: "r"(dB), "l"(srcB));
    }
    asm volatile("cp.async.commit_group;\n");
}

template <int EPI>
__device__ __forceinline__ void gemm_body(
    const __half* __restrict__ A, const __half* __restrict__ W,
    const float* __restrict__ bias, const float* __restrict__ resf,
    const __half* __restrict__ resh,
    float* __restrict__ C, __half* __restrict__ Ch,
    int M, int N, int K)
{
    extern __shared__ __half smh[];
    const u32 sbase = smem_u32(smh);

    const int tid    = threadIdx.x;
    const int lane   = tid & 31;
    const int wid    = tid >> 5;
    const int warp_m = wid & 3;
    const int warp_n = wid >> 2;
    const int m0 = blockIdx.y * GBM;
    const int n0 = blockIdx.x * GBN;
    const int mIdx = lane >> 3;
    const int rIn  = lane & 7;

    float acc[2][8][4];
#pragma unroll
    for (int i = 0; i < 2; i++)
#pragma unroll
        for (int j = 0; j < 8; j++)
#pragma unroll
            for (int k = 0; k < 4; k++) acc[i][j][k] = 0.f;

    const int ktiles = K / GBK;

    gemm_stage_load(A, W, M, K, m0, n0, 0, sbase, sbase + 3u*STG_HALVES*2, tid);
    gemm_stage_load(A, W, M, K, m0, n0, 1, sbase + 1u*STG_HALVES*2, sbase + 4u*STG_HALVES*2, tid);

    for (int kt = 0; kt < ktiles; kt++) {
        asm volatile("cp.async.wait_group 1;\n" ::: "memory");
        __syncthreads();

        if (kt + 2 < ktiles) {
            int slot = (kt + 2) % 3;
            gemm_stage_load(A, W, M, K, m0, n0, kt + 2,
                            sbase + (u32)slot * STG_HALVES * 2,
                            sbase + (u32)(3 + slot) * STG_HALVES * 2, tid);
        } else {
            asm volatile("cp.async.commit_group;\n");
        }

        const int slot = kt % 3;
        const u32 sA = sbase + (u32)slot * STG_HALVES * 2;
        const u32 sB = sbase + (u32)(3 + slot) * STG_HALVES * 2;

#pragma unroll
        for (int ks = 0; ks < 4; ks++) {
            u32 a00, a01, a02, a03, a10, a11, a12, a13;
            {
                int row   = warp_m * 32 + (mIdx & 1) * 8 + rIn;
                int chunk = ks * 2 + (mIdx >> 1);
                u32 ad0 = sA + (u32)(row * 64 + ((chunk ^ (row & 7)) << 3)) * 2;
                ldmx4(a00, a01, a02, a03, ad0);
                int row1 = row + 16;
                u32 ad1 = sA + (u32)(row1 * 64 + ((chunk ^ (row1 & 7)) << 3)) * 2;
                ldmx4(a10, a11, a12, a13, ad1);
            }
#pragma unroll
            for (int j = 0; j < 4; j++) {
                int nrow  = warp_n * 64 + j * 16 + (mIdx >> 1) * 8 + rIn;
                int chunk = ks * 2 + (mIdx & 1);
                u32 badr = sB + (u32)(nrow * 64 + ((chunk ^ (nrow & 7)) << 3)) * 2;
                u32 b0, b1, b2, b3;
                ldmx4(b0, b1, b2, b3, badr);
                mma16816(acc[0][2*j],   a00, a01, a02, a03, b0, b1);
                mma16816(acc[0][2*j+1], a00, a01, a02, a03, b2, b3);
                mma16816(acc[1][2*j],   a10, a11, a12, a13, b0, b1);
                mma16816(acc[1][2*j+1], a10, a11, a12, a13, b2, b3);
            }
        }
        // no trailing sync needed with 3-deep ring
    }

    const int g  = lane >> 2;
    const int tg = lane & 3;
#pragma unroll
    for (int mi = 0; mi < 2; mi++) {
#pragma unroll
        for (int ni = 0; ni < 8; ni++) {
            const int col = n0 + warp_n * 64 + ni * 8 + tg * 2;
            const float bc0 = bias[col], bc1 = bias[col + 1];
#pragma unroll
            for (int hh = 0; hh < 2; hh++) {
                int row = m0 + warp_m * 32 + mi * 16 + g + hh * 8;
                if (row < M) {
                    float v0 = acc[mi][ni][hh * 2 + 0] + bc0;
                    float v1 = acc[mi][ni][hh * 2 + 1] + bc1;
                    if (EPI == 2) {
                        v0 = __fdividef(v0, 1.f + exp2p(GELU_C * v0));
                        v1 = __fdividef(v1, 1.f + exp2p(GELU_C * v1));
                        *(__half2*)(Ch + (size_t)row * N + col) = __floats2half2_rn(v0, v1);
                    } else if (EPI == 4) {
                        *(__half2*)(Ch + (size_t)row * N + col) = __floats2half2_rn(v0, v1);
                    } else if (EPI == 5) {
                        const float2 rr = *(const float2*)(resf + (size_t)row * N + col);
                        v0 += rr.x; v1 += rr.y;
                        *(__half2*)(Ch + (size_t)row * N + col) = __floats2half2_rn(v0, v1);
                    } else if (EPI == 6) {
                        const __half2 rh = *(const __half2*)(resh + (size_t)row * N + col);
                        const float2 rr = __half22float2(rh);
                        v0 += rr.x; v1 += rr.y;
                        *(float2*)(C + (size_t)row * N + col) = make_float2(v0, v1);
                    }
                }
            }
        }
    }
}

template <int EPI>
__global__ __launch_bounds__(256, 2) void gemm16(
    const __half* __restrict__ A, const __half* __restrict__ W,
    const float* __restrict__ bias, const float* __restrict__ resf,
    const __half* __restrict__ resh,
    float* __restrict__ C, __half* __restrict__ Ch,
    int M, int N, int K)
{
    gemm_body<EPI>(A, W, bias, resf, resh, C, Ch, M, N, K);
}

// dual-problem GEMM (fills partial waves of small grids)
template <int EPI>
__global__ __launch_bounds__(256, 2) void gemm16_dual(
    const __half* __restrict__ A0, const __half* __restrict__ W0,
    const float* __restrict__ b0, __half* __restrict__ Ch0, int M0,
    const __half* __restrict__ A1, const __half* __restrict__ W1,
    const float* __restrict__ b1, __half* __restrict__ Ch1, int M1,
    int N, int K)
{
    if (blockIdx.z == 0)
        gemm_body<EPI>(A0, W0, b0, nullptr, nullptr, nullptr, Ch0, M0, N, K);
    else
        gemm_body<EPI>(A1, W1, b1, nullptr, nullptr, nullptr, Ch1, M1, N, K);
}

// ---------------------------------------------------------------------------
// Tensor-core flash attention (round-9 proven): one CTA per (bt, head),
// 544 threads = 17 warps, one 16-query tile per warp.
// ---------------------------------------------------------------------------
#define ATT_THREADS 544
#define QK_ROW 72
#define VT_ROW 280
#define LPAD   272
#define NKT    17
#define SK_OFF  (LPAD*QK_ROW)
#define SVT_OFF (2*LPAD*QK_ROW)
#define ATTN_SMEM ((SVT_OFF + HDIM*VT_ROW) * 2)
#define QSC 0.1803368801111244f   /* hd^-0.5 * log2(e) */

__global__ __launch_bounds__(ATT_THREADS, 1) void attn_mma(
    const __half* __restrict__ qkvh, __half* __restrict__ out)
{
    extern __shared__ __half smA[];
    __half* sQh  = smA;
    __half* sKh  = smA + SK_OFF;
    __half* sVth = smA + SVT_OFF;
    const u32 sQ  = smem_u32(smA);
    const u32 sK  = sQ + SK_OFF * 2;
    const u32 sVt = sQ + SVT_OFF * 2;

    const int bt = blockIdx.x >> 4;
    const int h  = blockIdx.x & 15;
    const int tid = threadIdx.x;
    const __half* base = qkvh + (size_t)bt * LL * (3 * DMODEL) + h * HDIM;

    for (int i = tid; i < LL * 16; i += ATT_THREADS) {
        int l = i >> 4, d4 = i & 15;
        const __half* p = base + (size_t)l * (3 * DMODEL) + d4 * 4;
        uint2 qr = *(const uint2*)(p);
        uint2 kr = *(const uint2*)(p + DMODEL);
        uint2 vr = *(const uint2*)(p + 2 * DMODEL);
        float2 qa = __half22float2(*(__half2*)&qr.x);
        float2 qb = __half22float2(*(__half2*)&qr.y);
        __half2* qd = (__half2*)(sQh + l * QK_ROW + d4 * 4);
        qd[0] = __floats2half2_rn(qa.x * QSC, qa.y * QSC);
        qd[1] = __floats2half2_rn(qb.x * QSC, qb.y * QSC);
        *(uint2*)(sKh + l * QK_ROW + d4 * 4) = kr;
        __half2 v01 = *(__half2*)&vr.x;
        __half2 v23 = *(__half2*)&vr.y;
        int d = d4 * 4;
        sVth[(d + 0) * VT_ROW + l] = __low2half(v01);
        sVth[(d + 1) * VT_ROW + l] = __high2half(v01);
        sVth[(d + 2) * VT_ROW + l] = __low2half(v23);
        sVth[(d + 3) * VT_ROW + l] = __high2half(v23);
    }
    for (int i = tid; i < 15 * HDIM; i += ATT_THREADS) {
        int l = LL + (i >> 6);
        int d = i & 63;
        __half z = __float2half(0.f);
        sQh[l * QK_ROW + d] = z;
        sKh[l * QK_ROW + d] = z;
        sVth[d * VT_ROW + l] = z;
    }
    __syncthreads();

    const int wid  = tid >> 5;
    const int lane = tid & 31;
    const int g    = lane >> 2;
    const int tg   = lane & 3;
    const int mIdx = lane >> 3;
    const int rIn  = lane & 7;
    const int qt   = wid;

    u32 aQ[4][4];
#pragma unroll
    for (int kc = 0; kc < 4; kc++) {
        int row   = qt * 16 + (mIdx & 1) * 8 + rIn;
        int chunk = kc * 2 + (mIdx >> 1);
        ldmx4(aQ[kc][0], aQ[kc][1], aQ[kc][2], aQ[kc][3],
              sQ + (u32)(row * QK_ROW + chunk * 8) * 2);
    }

    float m0 = -1e30f, m1 = -1e30f, l0 = 0.f, l1 = 0.f;
    float oacc[8][4];
#pragma unroll
    for (int n = 0; n < 8; n++)
#pragma unroll
        for (int j = 0; j < 4; j++) oacc[n][j] = 0.f;

    for (int kt = 0; kt < NKT; kt++) {
        float sf[2][4];
#pragma unroll
        for (int j = 0; j < 4; j++) { sf[0][j] = 0.f; sf[1][j] = 0.f; }
#pragma unroll
        for (int kc = 0; kc < 4; kc++) {
            int nrow  = kt * 16 + (mIdx >> 1) * 8 + rIn;
            int chunk = kc * 2 + (mIdx & 1);
            u32 b0, b1, b2, b3;
            ldmx4(b0, b1, b2, b3, sK + (u32)(nrow * QK_ROW + chunk * 8) * 2);
            mma16816(sf[0], aQ[kc][0], aQ[kc][1], aQ[kc][2], aQ[kc][3], b0, b1);
            mma16816(sf[1], aQ[kc][0], aQ[kc][1], aQ[kc][2], aQ[kc][3], b2, b3);
        }
        if (kt == 16) {
            bool v0 = (tg == 0);
            sf[0][0] = v0 ? sf[0][0] : -1e30f;
            sf[0][2] = v0 ? sf[0][2] : -1e30f;
            sf[0][1] = -1e30f; sf[0][3] = -1e30f;
            sf[1][0] = -1e30f; sf[1][1] = -1e30f;
            sf[1][2] = -1e30f; sf[1][3] = -1e30f;
        }
        float tm0 = fmaxf(fmaxf(sf[0][0], sf[0][1]), fmaxf(sf[1][0], sf[1][1]));
        float tm1 = fmaxf(fmaxf(sf[0][2], sf[0][3]), fmaxf(sf[1][2], sf[1][3]));
        tm0 = fmaxf(tm0, __shfl_xor_sync(0xffffffffu, tm0, 1));
        tm0 = fmaxf(tm0, __shfl_xor_sync(0xffffffffu, tm0, 2));
        tm1 = fmaxf(tm1, __shfl_xor_sync(0xffffffffu, tm1, 1));
        tm1 = fmaxf(tm1, __shfl_xor_sync(0xffffffffu, tm1, 2));
        if (tm0 > m0) {
            float c = exp2p(m0 - tm0);
            m0 = tm0; l0 *= c;
#pragma unroll
            for (int n = 0; n < 8; n++) { oacc[n][0] *= c; oacc[n][1] *= c; }
        }
        if (tm1 > m1) {
            float c = exp2p(m1 - tm1);
            m1 = tm1; l1 *= c;
#pragma unroll
            for (int n = 0; n < 8; n++) { oacc[n][2] *= c; oacc[n][3] *= c; }
        }
        float p00 = exp2p(sf[0][0] - m0), p01 = exp2p(sf[0][1] - m0);
        float p02 = exp2p(sf[1][0] - m0), p03 = exp2p(sf[1][1] - m0);
        float p10 = exp2p(sf[0][2] - m1), p11 = exp2p(sf[0][3] - m1);
        float p12 = exp2p(sf[1][2] - m1), p13 = exp2p(sf[1][3] - m1);
        l0 += (p00 + p01) + (p02 + p03);
        l1 += (p10 + p11) + (p12 + p13);
        u32 aP0 = h2u(__floats2half2_rn(p00, p01));
        u32 aP1 = h2u(__floats2half2_rn(p10, p11));
        u32 aP2 = h2u(__floats2half2_rn(p02, p03));
        u32 aP3 = h2u(__floats2half2_rn(p12, p13));
#pragma unroll
        for (int np = 0; np < 4; np++) {
            int nrow  = np * 16 + (mIdx >> 1) * 8 + rIn;
            int chunk = kt * 2 + (mIdx & 1);
            u32 b0, b1, b2, b3;
            ldmx4(b0, b1, b2, b3, sVt + (u32)(nrow * VT_ROW + chunk * 8) * 2);
            mma16816(oacc[2*np],     aP0, aP1, aP2, aP3, b0, b1);
            mma16816(oacc[2*np + 1], aP0, aP1, aP2, aP3, b2, b3);
        }
    }
    l0 += __shfl_xor_sync(0xffffffffu, l0, 1);
    l0 += __shfl_xor_sync(0xffffffffu, l0, 2);
    l1 += __shfl_xor_sync(0xffffffffu, l1, 1);
    l1 += __shfl_xor_sync(0xffffffffu, l1, 2);
    float inv0 = 1.f / l0, inv1 = 1.f / l1;
    int r0 = qt * 16 + g;
    int r1 = r0 + 8;
    if (r0 < LL) {
        __half2* o = (__half2*)(out + ((size_t)bt * LL + r0) * DMODEL + h * HDIM);
#pragma unroll
        for (int n = 0; n < 8; n++)
            o[(n * 8 + tg * 2) >> 1] = __floats2half2_rn(oacc[n][0] * inv0, oacc[n][1] * inv0);
    }
    if (r1 < LL) {
        __half2* o = (__half2*)(out + ((size_t)bt * LL + r1) * DMODEL + h * HDIM);
#pragma unroll
        for (int n = 0; n < 8; n++)
            o[(n * 8 + tg * 2) >> 1] = __floats2half2_rn(oacc[n][2] * inv1, oacc[n][3] * inv1);
    }
}

// ---------------------------------------------------------------------------
// Elementwise / conv kernels
// ---------------------------------------------------------------------------
// temporal diff of patch tokens, fp16 in / fp16 out
__global__ void diff_kernel(const __half* __restrict__ x1h, __half* __restrict__ diff)
{
    int i = blockIdx.x * blockDim.x + threadIdx.x;   // 4 elems per thread
    if (i >= MOFF * DMODEL / 4) return;
    int r = i >> 8;
    int p = r & 255;
    int f = r >> 8;
    int t = f & (TT - 1);
    size_t cur = ((size_t)f * LL + (p + 1)) * DMODEL + (size_t)(i & 255) * 4;
    uint2 v = *(const uint2*)(x1h + cur);
    uint2 pv = (t > 0) ? *(const uint2*)(x1h + cur - (size_t)LL * DMODEL) : v;
    __half2* o = (__half2*)(diff + (size_t)i * 4);
    o[0] = __hsub2(*(__half2*)&v.x, *(__half2*)&pv.x);
    o[1] = __hsub2(*(__half2*)&v.y, *(__half2*)&pv.y);
}

// merged depthwise convs (fp16 in/out)
__global__ void conv_merged(const __half* __restrict__ off1,
                            const float* __restrict__ ocw, const float* __restrict__ ocb,
                            __half* __restrict__ offc,
                            const __half* __restrict__ y1,
                            const float* __restrict__ acw, const float* __restrict__ acb,
                            __half* __restrict__ yc)
{
    int idx = blockIdx.x * blockDim.x + threadIdx.x;
    if (idx < MOFF * CA) {
        int c = idx % CA;
        int r = idx / CA;
        int p = r & 255;
        int n = r >> 8;
        int hh = p >> 4, ww = p & 15;
        float s = ocb[c];
#pragma unroll
        for (int dh = 0; dh < 3; dh++) {
            int h2 = hh + dh - 1;
            if (h2 < 0 || h2 > 15) continue;
#pragma unroll
            for (int dw = 0; dw < 3; dw++) {
                int w2 = ww + dw - 1;
                if (w2 < 0 || w2 > 15) continue;
                s += __half2float(off1[((size_t)(n * 256 + h2 * 16 + w2)) * CA + c])
                     * ocw[(dh * 3 + dw) * CA + c];
            }
        }
        offc[idx] = __float2half_rn(s);
    } else {
        int k = idx - MOFF * CA;
        if (k >= MROWS * CA) return;
        int c = k % CA;
        int row = k / CA;
        int l = row % LL;
        int bt = row / LL;
        int t = bt & (TT - 1);
        float s = acb[c];
#pragma unroll
        for (int dt = 0; dt < 3; dt++) {
            int tt = t + dt - 1;
            if (tt < 0 || tt >= TT) continue;
            s += __half2float(y1[((size_t)(bt + dt - 1) * LL + l) * CA + c]) * acw[dt * CA + c];
        }
        yc[k] = __float2half_rn(s);
    }
}

// ---------------------------------------------------------------------------
// Launch
// ---------------------------------------------------------------------------
extern "C" void kernel_launch(void* const* d_in, const int* in_sizes, int n_in,
                              void* d_out, int out_size)
{
    const float* x         = (const float*)d_in[0];
    const float* ln1_g     = (const float*)d_in[1];
    const float* ln1_b     = (const float*)d_in[2];
    const float* w_in      = (const float*)d_in[3];
    const float* b_in      = (const float*)d_in[4];
    const float* w_out     = (const float*)d_in[5];
    const float* b_out     = (const float*)d_in[6];
    const float* o_fc1_w   = (const float*)d_in[7];
    const float* o_fc1_b   = (const float*)d_in[8];
    const float* o_conv_w  = (const float*)d_in[9];
    const float* o_conv_b  = (const float*)d_in[10];
    const float* o_fc2_w   = (const float*)d_in[11];
    const float* o_fc2_b   = (const float*)d_in[12];
    const float* a_fc1_w   = (const float*)d_in[13];
    const float* a_fc1_b   = (const float*)d_in[14];
    const float* a_conv_w  = (const float*)d_in[15];
    const float* a_conv_b  = (const float*)d_in[16];
    const float* a_fc2_w   = (const float*)d_in[17];
    const float* a_fc2_b   = (const float*)d_in[18];
    const float* ln2_g     = (const float*)d_in[19];
    const float* ln2_b     = (const float*)d_in[20];
    const float* mlp_fc_w  = (const float*)d_in[21];
    const float* mlp_fc_b  = (const float*)d_in[22];
    const float* mlp_proj_w= (const float*)d_in[23];
    const float* mlp_proj_b= (const float*)d_in[24];
    float* outp = (float*)d_out;

    __half *x2h, *off2h, *y2h;
    __half *qkvh, *lnh, *attnh, *x1h, *diffh, *off1h, *offch, *y1h, *ych, *hhp;
    __half *win, *wout, *wofc1, *wofc2, *wafc1, *wafc2, *wmfc, *wmpj;
    cudaGetSymbolAddress((void**)&x2h,  h_x2);
    cudaGetSymbolAddress((void**)&off2h,h_off2);
    cudaGetSymbolAddress((void**)&y2h,  h_y2);
    cudaGetSymbolAddress((void**)&qkvh, h_qkv);
    cudaGetSymbolAddress((void**)&lnh,  h_ln);
    cudaGetSymbolAddress((void**)&attnh,h_attn);
    cudaGetSymbolAddress((void**)&x1h,  h_x1);
    cudaGetSymbolAddress((void**)&diffh,h_diff);
    cudaGetSymbolAddress((void**)&off1h,h_off1);
    cudaGetSymbolAddress((void**)&offch,h_offc);
    cudaGetSymbolAddress((void**)&y1h,  h_y1);
    cudaGetSymbolAddress((void**)&ych,  h_yc);
    cudaGetSymbolAddress((void**)&hhp,  h_h);
    cudaGetSymbolAddress((void**)&win,  wh_in);
    cudaGetSymbolAddress((void**)&wout, wh_out);
    cudaGetSymbolAddress((void**)&wofc1,wh_ofc1);
    cudaGetSymbolAddress((void**)&wofc2,wh_ofc2);
    cudaGetSymbolAddress((void**)&wafc1,wh_afc1);
    cudaGetSymbolAddress((void**)&wafc2,wh_afc2);
    cudaGetSymbolAddress((void**)&wmfc, wh_mfc);
    cudaGetSymbolAddress((void**)&wmpj, wh_mpj);

    cudaFuncSetAttribute(attn_mma, cudaFuncAttributeMaxDynamicSharedMemorySize, ATTN_SMEM);
    cudaFuncSetAttribute(gemm16<2>, cudaFuncAttributeMaxDynamicSharedMemorySize, GEMM_SMEM);
    cudaFuncSetAttribute(gemm16<4>, cudaFuncAttributeMaxDynamicSharedMemorySize, GEMM_SMEM);
    cudaFuncSetAttribute(gemm16<5>, cudaFuncAttributeMaxDynamicSharedMemorySize, GEMM_SMEM);
    cudaFuncSetAttribute(gemm16<6>, cudaFuncAttributeMaxDynamicSharedMemorySize, GEMM_SMEM);
    cudaFuncSetAttribute(gemm16_dual<4>, cudaFuncAttributeMaxDynamicSharedMemorySize, GEMM_SMEM);

    const int EW = 256;
    const int gy_full = (MROWS + GBM - 1) / GBM;  // 129

    // 1) all weight conversions in ONE launch
    {
        F2HArgs a;
        a.src[0] = w_in;       a.dst[0] = win;   a.n4[0] = 3*DMODEL*DMODEL/4;
        a.src[1] = w_out;      a.dst[1] = wout;  a.n4[1] = DMODEL*DMODEL/4;
        a.src[2] = mlp_fc_w;   a.dst[2] = wmfc;  a.n4[2] = 4*DMODEL*DMODEL/4;
        a.src[3] = mlp_proj_w; a.dst[3] = wmpj;  a.n4[3] = 4*DMODEL*DMODEL/4;
        a.src[4] = o_fc1_w;    a.dst[4] = wofc1; a.n4[4] = CA*DMODEL/4;
        a.src[5] = o_fc2_w;    a.dst[5] = wofc2; a.n4[5] = DMODEL*CA/4;
        a.src[6] = a_fc1_w;    a.dst[6] = wafc1; a.n4[6] = CA*DMODEL/4;
        a.src[7] = a_fc2_w;    a.dst[7] = wafc2; a.n4[7] = DMODEL*CA/4;
        int tot = 0;
        for (int t = 0; t < 8; t++) tot += a.n4[t];
        f2h_oct<<<(tot + 255)/256, 256>>>(a);
    }

    // 2) ln1
    ln_kernel<<<MROWS, 256>>>(x, ln1_g, ln1_b, lnh);
    // 3) qkv (fp16 out)
    gemm16<4><<<dim3(3*DMODEL/GBN, gy_full), 256, GEMM_SMEM>>>(lnh, win, b_in, nullptr, nullptr, nullptr, qkvh, MROWS, 3*DMODEL, DMODEL);
    // 4) attention — profiled slot
    attn_mma<<<BT * NHEAD, ATT_THREADS, ATTN_SMEM>>>(qkvh, attnh);
    // 5) out-proj + residual(x fp32) -> x1h fp16 only
    gemm16<5><<<dim3(DMODEL/GBN, gy_full), 256, GEMM_SMEM>>>(attnh, wout, b_out, x, nullptr, nullptr, x1h, MROWS, DMODEL, DMODEL);
    // 6) temporal diff (fp16 in/out)
    diff_kernel<<<(MOFF*DMODEL/4 + EW - 1)/EW, EW>>>(x1h, diffh);
    // 7) BOTH fc1 GEMMs in one launch, fp16 out
    gemm16_dual<4><<<dim3(CA/GBN, gy_full, 2), 256, GEMM_SMEM>>>(
        diffh, wofc1, o_fc1_b, off1h, MOFF,
        x1h,   wafc1, a_fc1_b, y1h,   MROWS, CA, DMODEL);
    // 8) BOTH depthwise convs in one launch
    conv_merged<<<((MOFF + MROWS)*CA + EW - 1)/EW, EW>>>(
        off1h, o_conv_w, o_conv_b, offch, y1h, a_conv_w, a_conv_b, ych);
    // 9) BOTH fc2 GEMMs in one launch, fp16 out
    gemm16_dual<4><<<dim3(DMODEL/GBN, gy_full, 2), 256, GEMM_SMEM>>>(
        offch, wofc2, o_fc2_b, off2h, MOFF,
        ych,   wafc2, a_fc2_b, y2h,   MROWS, DMODEL, CA);
    // 10) fused combine + ln2 (all-fp16 residual stream)
    combine_ln_kernel<<<MROWS, 256>>>(x1h, y2h, off2h, ln2_g, ln2_b, x2h, lnh);
    // 11) MLP fc + QuickGELU
    gemm16<2><<<dim3(4*DMODEL/GBN, gy_full), 256, GEMM_SMEM>>>(lnh, wmfc, mlp_fc_b, nullptr, nullptr, nullptr, hhp, MROWS, 4*DMODEL, DMODEL);
    // 12) MLP proj + residual(x2h fp16) -> fp32 output
    gemm16<6><<<dim3(DMODEL/GBN, gy_full), 256, GEMM_SMEM>>>(hhp, wmpj, mlp_proj_b, nullptr, x2h, outp, nullptr, MROWS, DMODEL, 4*DMODEL);
}